// round 5
// baseline (speedup 1.0000x reference)
#include <cuda_runtime.h>
#include <math.h>

#define NB 8
#define NT 2048
#define NE 64
#define NH 8
#define NDK 8
#define NFF 256
#define NROWS (NB*NT)

typedef unsigned long long u64;

__device__ __forceinline__ u64 pk2(float x, float y){ u64 r; asm("mov.b64 %0,{%1,%2};":"=l"(r):"f"(x),"f"(y)); return r; }
__device__ __forceinline__ void upk2(float&x,float&y,u64 v){ asm("mov.b64 {%0,%1},%2;":"=f"(x),"=f"(y):"l"(v)); }
__device__ __forceinline__ u64 ffma2(u64 a,u64 b,u64 c){ u64 r; asm("fma.rn.f32x2 %0,%1,%2,%3;":"=l"(r):"l"(a),"l"(b),"l"(c)); return r; }
__device__ __forceinline__ u64 fadd2(u64 a,u64 b){ u64 r; asm("add.rn.f32x2 %0,%1,%2;":"=l"(r):"l"(a),"l"(b)); return r; }

// ---- scratch ----
__device__ float g_q[NROWS*NE];     // row-major, col = h*8+d, pre-scaled 1/sqrt(8)
__device__ float g_k[NROWS*NE];
__device__ float g_v[NROWS*NE];
__device__ float g_attn[NROWS*NE];
__device__ float g_Wot[NE*NE];      // [e][j]
__device__ float g_W1t[NE*NFF];     // [e][f]
__device__ float g_W2t[NFF*NE];     // [f][j]

__global__ void k_transpose(const float* __restrict__ W1, const float* __restrict__ W2,
                            const float* __restrict__ Wo){
    int i = blockIdx.x*256 + threadIdx.x;
    if (i < NE*NFF){
        int e = i / NFF, f = i % NFF;
        g_W1t[i] = W1[f*NE + e];
        int f2 = i / NE, j = i % NE;
        g_W2t[i] = W2[j*NFF + f2];
    }
    if (i < NE*NE){
        int e = i >> 6, j = i & 63;
        g_Wot[i] = Wo[j*NE + e];
    }
}

// ---- K1: QKV (all three projections in one pass) + cos(.+theta) ----
// 32 rows/block, 512 blocks, 256 threads. thread = 4 rows x 1 col-pair x 3 mats.
#define QKV_SMEM ((32*130 + 3*64*66)*4)
__global__ __launch_bounds__(256) void k_qkv(
    const float* __restrict__ x,
    const float* __restrict__ Wq, const float* __restrict__ bq,
    const float* __restrict__ Wk, const float* __restrict__ bk,
    const float* __restrict__ Wv, const float* __restrict__ bv,
    const float* __restrict__ th)
{
    extern __shared__ float sm[];
    float* xs2 = sm;            // [32][130] duplicated pairs
    float* Wt  = sm + 32*130;   // [3][64][66]
    int tid = threadIdx.x;
    int row0 = blockIdx.x*32;

    for (int i = tid; i < 32*64; i += 256){
        int r = i >> 6, c = i & 63;
        float v = x[(u64)(row0 + r)*NE + c];
        *(u64*)(xs2 + r*130 + c*2) = pk2(v, v);
    }
    for (int i = tid; i < 4096; i += 256){
        int j = i >> 6, e = i & 63;
        Wt[          e*66 + j] = Wq[j*64 + e];
        Wt[4224    + e*66 + j] = Wk[j*64 + e];
        Wt[2*4224  + e*66 + j] = Wv[j*64 + e];
    }
    __syncthreads();

    const float theta = *th;
    int j2 = tid & 31, g = tid >> 5;
    int j0 = j2*2;
    u64 aq[4] = {0,0,0,0}, ak[4] = {0,0,0,0}, av[4] = {0,0,0,0};
    const float* xb = xs2 + (g*4)*130;
    #pragma unroll 4
    for (int e = 0; e < 64; ++e){
        u64 wq = *(const u64*)(Wt +          e*66 + j0);
        u64 wk = *(const u64*)(Wt + 4224   + e*66 + j0);
        u64 wv = *(const u64*)(Wt + 2*4224 + e*66 + j0);
        #pragma unroll
        for (int r = 0; r < 4; ++r){
            u64 xv = *(const u64*)(xb + r*130 + e*2);
            aq[r] = ffma2(xv, wq, aq[r]);
            ak[r] = ffma2(xv, wk, ak[r]);
            av[r] = ffma2(xv, wv, av[r]);
        }
    }
    float2 b_q = *(const float2*)(bq + j0);
    float2 b_k = *(const float2*)(bk + j0);
    float2 b_v = *(const float2*)(bv + j0);
    #pragma unroll
    for (int r = 0; r < 4; ++r){
        u64 off = (u64)(row0 + g*4 + r)*NE + j0;
        float a0, a1;
        upk2(a0, a1, aq[r]);
        float2 o;
        o.x = cosf(a0 + b_q.x + theta) * 0.35355339059327373f;
        o.y = cosf(a1 + b_q.y + theta) * 0.35355339059327373f;
        *(float2*)(g_q + off) = o;
        upk2(a0, a1, ak[r]);
        o.x = cosf(a0 + b_k.x + theta);
        o.y = cosf(a1 + b_k.y + theta);
        *(float2*)(g_k + off) = o;
        upk2(a0, a1, av[r]);
        o.x = cosf(a0 + b_v.x + theta);
        o.y = cosf(a1 + b_v.y + theta);
        *(float2*)(g_v + off) = o;
    }
}

// ---- K2: attention. 1024 threads (32 warps, 100% occ), 1 query/thread. ----
__global__ void __launch_bounds__(1024,1) k_attn()
{
    extern __shared__ float sm[];
    float* Ks = sm;                 // [8][2048]
    float* Vs = sm + NDK*NT;
    int bh  = blockIdx.y;
    int b = bh >> 3, h = bh & 7;
    int tid = threadIdx.x;
    const float* kg = g_k + (u64)b*NT*NE + h*8;
    const float* vg = g_v + (u64)b*NT*NE + h*8;
    for (int i = tid; i < 2*NT; i += 1024){
        int t = i & (NT-1), half = (i >> 11)*4;
        float4 kv = *(const float4*)(kg + (u64)t*NE + half);
        Ks[(half+0)*NT + t] = kv.x; Ks[(half+1)*NT + t] = kv.y;
        Ks[(half+2)*NT + t] = kv.z; Ks[(half+3)*NT + t] = kv.w;
        float4 vv = *(const float4*)(vg + (u64)t*NE + half);
        Vs[(half+0)*NT + t] = vv.x; Vs[(half+1)*NT + t] = vv.y;
        Vs[(half+2)*NT + t] = vv.z; Vs[(half+3)*NT + t] = vv.w;
    }
    __syncthreads();

    int q = blockIdx.x*1024 + tid;
    const float* qp = g_q + (u64)(b*NT + q)*NE + h*8;
    float4 qa = *(const float4*)qp;
    float4 qb = *((const float4*)qp + 1);
    u64 q2[8];
    q2[0] = pk2(qa.x, qa.x); q2[1] = pk2(qa.y, qa.y);
    q2[2] = pk2(qa.z, qa.z); q2[3] = pk2(qa.w, qa.w);
    q2[4] = pk2(qb.x, qb.x); q2[5] = pk2(qb.y, qb.y);
    q2[6] = pk2(qb.z, qb.z); q2[7] = pk2(qb.w, qb.w);
    u64 o2[8];
    #pragma unroll
    for (int d = 0; d < 8; ++d) o2[d] = 0ull;
    u64 lsum = 0ull;

    #pragma unroll 1
    for (int s = 0; s < NT; s += 4){
        u64 sA = 0ull, sB = 0ull;
        #pragma unroll
        for (int d = 0; d < 8; ++d){
            const u64* kp = (const u64*)(Ks + d*NT + s);
            sA = ffma2(q2[d], kp[0], sA);
            sB = ffma2(q2[d], kp[1], sB);
        }
        float a, bb, c, dd;
        upk2(a, bb, sA); upk2(c, dd, sB);
        a = __expf(a); bb = __expf(bb); c = __expf(c); dd = __expf(dd);
        u64 pA = pk2(a, bb), pB = pk2(c, dd);
        lsum = fadd2(lsum, fadd2(pA, pB));
        #pragma unroll
        for (int d = 0; d < 8; ++d){
            const u64* vp = (const u64*)(Vs + d*NT + s);
            o2[d] = ffma2(pA, vp[0], o2[d]);
            o2[d] = ffma2(pB, vp[1], o2[d]);
        }
    }

    float lx, ly; upk2(lx, ly, lsum);
    float inv = 1.0f / (lx + ly);
    float* dst = g_attn + (u64)(b*NT + q)*NE + h*8;
    float o[8];
    #pragma unroll
    for (int d = 0; d < 8; ++d){
        float ox, oy; upk2(ox, oy, o2[d]);
        o[d] = (ox + oy) * inv;
    }
    *(float4*)dst       = make_float4(o[0],o[1],o[2],o[3]);
    *((float4*)dst + 1) = make_float4(o[4],o[5],o[6],o[7]);
}

// ---- K3: fused tail: Wo proj + res + LN1 + qout + FFN1(relu) + FFN2 + res + LN2 ----
// 32 rows/block, 512 blocks, 256 threads. Weights from gmem (L2-hot).
#define TAIL_SMEM ((32*130 + 32*64 + 32*130 + 32*260)*4)
__global__ __launch_bounds__(256) void k_tail(
    const float* __restrict__ x,  const float* __restrict__ bo,
    const float* __restrict__ g1, const float* __restrict__ be1,
    const float* __restrict__ thf,
    const float* __restrict__ b1, const float* __restrict__ b2,
    const float* __restrict__ g2, const float* __restrict__ be2,
    float* __restrict__ out)
{
    extern __shared__ float sm[];
    float* adup = sm;                      // [32][130]
    float* x1s  = sm + 32*130;             // [32][64]
    float* qdup = sm + 32*130 + 32*64;     // [32][130]
    float* hs   = qdup + 32*130;           // [32][260]
    int tid = threadIdx.x;
    int row0 = blockIdx.x*32;

    for (int i = tid; i < 32*64; i += 256){
        int r = i >> 6, c = i & 63;
        float v = g_attn[(u64)(row0 + r)*NE + c];
        *(u64*)(adup + r*130 + c*2) = pk2(v, v);
    }
    __syncthreads();

    // Stage A: Wo proj + residual + LN1 + qout
    {
        int j2 = tid & 31, g = tid >> 5;
        int j0 = j2*2;
        u64 acc[4] = {0,0,0,0};
        const float* ab = adup + (g*4)*130;
        #pragma unroll 8
        for (int e = 0; e < 64; ++e){
            u64 w = *(const u64*)(g_Wot + e*64 + j0);
            acc[0] = ffma2(*(const u64*)(ab +       e*2), w, acc[0]);
            acc[1] = ffma2(*(const u64*)(ab + 130 + e*2), w, acc[1]);
            acc[2] = ffma2(*(const u64*)(ab + 260 + e*2), w, acc[2]);
            acc[3] = ffma2(*(const u64*)(ab + 390 + e*2), w, acc[3]);
        }
        float2 bo2  = *(const float2*)(bo + j0);
        float2 g12  = *(const float2*)(g1 + j0);
        float2 be12 = *(const float2*)(be1 + j0);
        float ct = cosf(*thf);
        #pragma unroll
        for (int r = 0; r < 4; ++r){
            int lr = g*4 + r;
            float2 xr = *(const float2*)(x + (u64)(row0 + lr)*NE + j0);
            float a0, a1; upk2(a0, a1, acc[r]);
            a0 += bo2.x + xr.x;
            a1 += bo2.y + xr.y;
            float s = a0 + a1;
            #pragma unroll
            for (int o = 16; o > 0; o >>= 1) s += __shfl_xor_sync(0xffffffffu, s, o);
            float mean = s * (1.0f/64.0f);
            float d0 = a0 - mean, d1 = a1 - mean;
            float vs = d0*d0 + d1*d1;
            #pragma unroll
            for (int o = 16; o > 0; o >>= 1) vs += __shfl_xor_sync(0xffffffffu, vs, o);
            float rstd = rsqrtf(vs * (1.0f/64.0f) + 1e-5f);
            float y0 = d0*rstd*g12.x + be12.x;
            float y1 = d1*rstd*g12.y + be12.y;
            x1s[lr*64 + j0]     = y0;
            x1s[lr*64 + j0 + 1] = y1;
            float q0v = cosf(y0)*ct, q1v = cosf(y1)*ct;
            *(u64*)(qdup + lr*130 + j0*2)     = pk2(q0v, q0v);
            *(u64*)(qdup + lr*130 + j0*2 + 2) = pk2(q1v, q1v);
        }
    }
    __syncthreads();

    // Stage B: FFN1 = relu(qout @ W1^T + b1) -> hs
    {
        int cq = tid & 63, rg = tid >> 6;   // rows rg*8..+7, col pairs c0, c0+128
        int c0 = cq*2;
        u64 f1[8][2];
        #pragma unroll
        for (int i = 0; i < 8; ++i){ f1[i][0] = 0ull; f1[i][1] = 0ull; }
        const float* qb = qdup + (rg*8)*130;
        #pragma unroll 4
        for (int e = 0; e < 64; ++e){
            u64 w0 = *(const u64*)(g_W1t + e*NFF + c0);
            u64 w1 = *(const u64*)(g_W1t + e*NFF + c0 + 128);
            #pragma unroll
            for (int i = 0; i < 8; ++i){
                u64 xv = *(const u64*)(qb + i*130 + e*2);
                f1[i][0] = ffma2(xv, w0, f1[i][0]);
                f1[i][1] = ffma2(xv, w1, f1[i][1]);
            }
        }
        float2 ba = *(const float2*)(b1 + c0);
        float2 bb = *(const float2*)(b1 + c0 + 128);
        #pragma unroll
        for (int i = 0; i < 8; ++i){
            int lr = rg*8 + i;
            float a0,a1,a2,a3;
            upk2(a0, a1, f1[i][0]);
            upk2(a2, a3, f1[i][1]);
            float2 o0; o0.x = fmaxf(a0 + ba.x, 0.f); o0.y = fmaxf(a1 + ba.y, 0.f);
            float2 o1; o1.x = fmaxf(a2 + bb.x, 0.f); o1.y = fmaxf(a3 + bb.y, 0.f);
            *(float2*)(hs + lr*260 + c0)       = o0;
            *(float2*)(hs + lr*260 + c0 + 128) = o1;
        }
    }
    __syncthreads();

    // Stage C: FFN2 + residual + LN2 -> out (scalar FMA, broadcast LDS)
    {
        int cp = tid & 31, ry = tid >> 5;   // col pair j0, rows ry*4..+3
        int j0 = cp*2;
        float c0a[4] = {0,0,0,0}, c1a[4] = {0,0,0,0};
        const float* hb = hs + (ry*4)*260;
        #pragma unroll 4
        for (int f = 0; f < 256; ++f){
            float2 w = *(const float2*)(g_W2t + f*NE + j0);
            #pragma unroll
            for (int r = 0; r < 4; ++r){
                float hv = hb[r*260 + f];
                c0a[r] = fmaf(hv, w.x, c0a[r]);
                c1a[r] = fmaf(hv, w.y, c1a[r]);
            }
        }
        float2 b4  = *(const float2*)(b2 + j0);
        float2 g24 = *(const float2*)(g2 + j0);
        float2 be24= *(const float2*)(be2 + j0);
        #pragma unroll
        for (int r = 0; r < 4; ++r){
            int lr = ry*4 + r;
            int row = row0 + lr;
            float a0 = c0a[r] + b4.x + x1s[lr*64 + j0];
            float a1 = c1a[r] + b4.y + x1s[lr*64 + j0 + 1];
            float s = a0 + a1;
            #pragma unroll
            for (int o = 16; o > 0; o >>= 1) s += __shfl_xor_sync(0xffffffffu, s, o);
            float mean = s * (1.0f/64.0f);
            float d0 = a0 - mean, d1 = a1 - mean;
            float vs = d0*d0 + d1*d1;
            #pragma unroll
            for (int o = 16; o > 0; o >>= 1) vs += __shfl_xor_sync(0xffffffffu, vs, o);
            float rstd = rsqrtf(vs * (1.0f/64.0f) + 1e-5f);
            float2 y;
            y.x = d0*rstd*g24.x + be24.x;
            y.y = d1*rstd*g24.y + be24.y;
            *(float2*)(out + (u64)row*NE + j0) = y;
        }
    }
}

extern "C" void kernel_launch(void* const* d_in, const int* in_sizes, int n_in,
                              void* d_out, int out_size)
{
    const float* x   = (const float*)d_in[0];
    const float* Wq  = (const float*)d_in[1];
    const float* bq  = (const float*)d_in[2];
    const float* Wk  = (const float*)d_in[3];
    const float* bk  = (const float*)d_in[4];
    const float* Wv  = (const float*)d_in[5];
    const float* bv  = (const float*)d_in[6];
    const float* Wo  = (const float*)d_in[7];
    const float* bo  = (const float*)d_in[8];
    const float* tha = (const float*)d_in[9];
    const float* thf = (const float*)d_in[10];
    const float* W1  = (const float*)d_in[11];
    const float* b1  = (const float*)d_in[12];
    const float* W2  = (const float*)d_in[13];
    const float* b2  = (const float*)d_in[14];
    const float* g1  = (const float*)d_in[15];
    const float* be1 = (const float*)d_in[16];
    const float* g2  = (const float*)d_in[17];
    const float* be2 = (const float*)d_in[18];
    float* out = (float*)d_out;

    cudaFuncSetAttribute(k_qkv,  cudaFuncAttributeMaxDynamicSharedMemorySize, QKV_SMEM);
    cudaFuncSetAttribute(k_attn, cudaFuncAttributeMaxDynamicSharedMemorySize, 131072);
    cudaFuncSetAttribute(k_tail, cudaFuncAttributeMaxDynamicSharedMemorySize, TAIL_SMEM);

    k_transpose<<<64, 256>>>(W1, W2, Wo);
    k_qkv<<<NROWS/32, 256, QKV_SMEM>>>(x, Wq, bq, Wk, bk, Wv, bv, tha);
    k_attn<<<dim3(2, 64), 1024, 131072>>>();
    k_tail<<<NROWS/32, 256, TAIL_SMEM>>>(x, bo, g1, be1, thf, b1, b2, g2, be2, out);
}

// round 6
// speedup vs baseline: 1.3031x; 1.3031x over previous
#include <cuda_runtime.h>
#include <math.h>

#define NB 8
#define NT 2048
#define NE 64
#define NH 8
#define NDK 8
#define NFF 256
#define NROWS (NB*NT)

typedef unsigned long long u64;
typedef unsigned u32;

__device__ __forceinline__ u64 pk2(float x, float y){ u64 r; asm("mov.b64 %0,{%1,%2};":"=l"(r):"f"(x),"f"(y)); return r; }
__device__ __forceinline__ void upk2(float&x,float&y,u64 v){ asm("mov.b64 {%0,%1},%2;":"=f"(x),"=f"(y):"l"(v)); }
__device__ __forceinline__ u64 ffma2(u64 a,u64 b,u64 c){ u64 r; asm("fma.rn.f32x2 %0,%1,%2,%3;":"=l"(r):"l"(a),"l"(b),"l"(c)); return r; }
__device__ __forceinline__ u32 cvt_tf32(float x){ u32 r; asm("cvt.rna.tf32.f32 %0,%1;":"=r"(r):"f"(x)); return r; }
__device__ __forceinline__ void mma_tf32(float&c0,float&c1,float&c2,float&c3,
                                         u32 a0,u32 a1,u32 a2,u32 a3,u32 b0,u32 b1){
    asm("mma.sync.aligned.m16n8k8.row.col.f32.tf32.tf32.f32 "
        "{%0,%1,%2,%3},{%4,%5,%6,%7},{%8,%9},{%0,%1,%2,%3};"
        : "+f"(c0),"+f"(c1),"+f"(c2),"+f"(c3)
        : "r"(a0),"r"(a1),"r"(a2),"r"(a3),"r"(b0),"r"(b1));
}

// ---- scratch ----
// Q/K/V per-head contiguous: [b*8+h][t][8]. Q pre-scaled by 1/sqrt(8).
__device__ float g_q[NROWS*NE];
__device__ float g_k[NROWS*NE];
__device__ float g_v[NROWS*NE];
__device__ float g_attn[NROWS*NE];   // row-major [b*T+t][64]
__device__ float g_x1[NROWS*NE];
__device__ float g_qout[NROWS*NE];
__device__ float g_hid[NROWS*NFF];
__device__ float g_W1t[NE*NFF];      // [e][f]
__device__ float g_W2t[NFF*NE];      // [f][j]

__global__ void k_transpose(const float* __restrict__ W1, const float* __restrict__ W2){
    int i = blockIdx.x*256 + threadIdx.x;
    if (i < NE*NFF){
        int e = i / NFF, f = i % NFF;
        g_W1t[i] = W1[f*NE + e];
        int f2 = i / NE, j = i % NE;
        g_W2t[i] = W2[j*NFF + f2];
    }
}

// ---- K1: QKV (merged single pass) + cos(.+theta), per-head output layout ----
#define QKV_SMEM ((32*130 + 3*64*66)*4)
__global__ __launch_bounds__(256) void k_qkv(
    const float* __restrict__ x,
    const float* __restrict__ Wq, const float* __restrict__ bq,
    const float* __restrict__ Wk, const float* __restrict__ bk,
    const float* __restrict__ Wv, const float* __restrict__ bv,
    const float* __restrict__ th)
{
    extern __shared__ float sm[];
    float* xs2 = sm;            // [32][130] duplicated pairs
    float* Wt  = sm + 32*130;   // [3][64][66]
    int tid = threadIdx.x;
    int row0 = blockIdx.x*32;
    int b = row0 >> 11, t0 = row0 & (NT-1);

    for (int i = tid; i < 32*64; i += 256){
        int r = i >> 6, c = i & 63;
        float v = x[(u64)(row0 + r)*NE + c];
        *(u64*)(xs2 + r*130 + c*2) = pk2(v, v);
    }
    for (int i = tid; i < 4096; i += 256){
        int j = i >> 6, e = i & 63;
        Wt[          e*66 + j] = Wq[j*64 + e];
        Wt[4224    + e*66 + j] = Wk[j*64 + e];
        Wt[2*4224  + e*66 + j] = Wv[j*64 + e];
    }
    __syncthreads();

    const float theta = *th;
    int j2 = tid & 31, g = tid >> 5;
    int j0 = j2*2;
    int h = j0 >> 3, d = j0 & 7;
    u64 aq[4] = {0,0,0,0}, ak[4] = {0,0,0,0}, av[4] = {0,0,0,0};
    const float* xb = xs2 + (g*4)*130;
    #pragma unroll 4
    for (int e = 0; e < 64; ++e){
        u64 wq = *(const u64*)(Wt +          e*66 + j0);
        u64 wk = *(const u64*)(Wt + 4224   + e*66 + j0);
        u64 wv = *(const u64*)(Wt + 2*4224 + e*66 + j0);
        #pragma unroll
        for (int r = 0; r < 4; ++r){
            u64 xv = *(const u64*)(xb + r*130 + e*2);
            aq[r] = ffma2(xv, wq, aq[r]);
            ak[r] = ffma2(xv, wk, ak[r]);
            av[r] = ffma2(xv, wv, av[r]);
        }
    }
    float2 b_q = *(const float2*)(bq + j0);
    float2 b_k = *(const float2*)(bk + j0);
    float2 b_v = *(const float2*)(bv + j0);
    #pragma unroll
    for (int r = 0; r < 4; ++r){
        int t = t0 + g*4 + r;
        u64 off = ((u64)(b*NH + h)*NT + t)*NDK + d;
        float a0, a1;
        upk2(a0, a1, aq[r]);
        float2 o;
        o.x = cosf(a0 + b_q.x + theta) * 0.35355339059327373f;
        o.y = cosf(a1 + b_q.y + theta) * 0.35355339059327373f;
        *(float2*)(g_q + off) = o;
        upk2(a0, a1, ak[r]);
        o.x = cosf(a0 + b_k.x + theta);
        o.y = cosf(a1 + b_k.y + theta);
        *(float2*)(g_k + off) = o;
        upk2(a0, a1, av[r]);
        o.x = cosf(a0 + b_v.x + theta);
        o.y = cosf(a1 + b_v.y + theta);
        *(float2*)(g_v + off) = o;
    }
}

// ---- K2: flash attention via mma.sync m16n8k8 tf32 ----
// Block: 512 threads = 16 warps, each warp = 16 queries -> 256 q/block.
// Full K (64KB) + V (64KB) in smem as tf32-bit pairs. Grid (8, 64).
// No-max softmax (scores bounded by 2.83).
__global__ void __launch_bounds__(512,1) k_attn()
{
    extern __shared__ u32 smu[];
    u32* Kp = smu;           // pair j = t*4+c : (K[t][c], K[t][c+4]) -> 2 uints
    u32* Vt = smu + 16384;   // pair j = g8*32 + d*4 + c : (V[8g8+c][d], V[8g8+c+4][d])
    int bh = blockIdx.y;
    int tid = threadIdx.x;
    const float* kg = g_k + (u64)bh*NT*NDK;
    const float* vg = g_v + (u64)bh*NT*NDK;
    for (int j = tid; j < 8192; j += 512){
        int t = j >> 2, c = j & 3;
        u32 lo = cvt_tf32(kg[t*8 + c]);
        u32 hi = cvt_tf32(kg[t*8 + c + 4]);
        *(uint2*)(Kp + j*2) = make_uint2(lo, hi);
        int g8 = j >> 5, d = (j >> 2) & 7, cc = j & 3;
        u32 vlo = cvt_tf32(vg[(8*g8 + cc)*8 + d]);
        u32 vhi = cvt_tf32(vg[(8*g8 + cc + 4)*8 + d]);
        *(uint2*)(Vt + j*2) = make_uint2(vlo, vhi);
    }
    __syncthreads();

    int wid = tid >> 5, lane = tid & 31;
    int g = lane >> 2, c = lane & 3;
    int qbase = blockIdx.x*256 + wid*16;
    int b = bh >> 3, h = bh & 7;

    // Q A-fragment (constant over the whole key loop)
    const float* qg = g_q + (u64)bh*NT*NDK;
    u32 qa0 = cvt_tf32(qg[(qbase + g    )*8 + c    ]);
    u32 qa1 = cvt_tf32(qg[(qbase + g + 8)*8 + c    ]);
    u32 qa2 = cvt_tf32(qg[(qbase + g    )*8 + c + 4]);
    u32 qa3 = cvt_tf32(qg[(qbase + g + 8)*8 + c + 4]);

    float o0 = 0.f, o1 = 0.f, o2 = 0.f, o3 = 0.f;
    float ls0 = 0.f, ls1 = 0.f;
    int sA = (lane & ~3) | (c >> 1);
    int sB = sA + 2;
    bool odd = (c & 1) != 0;

    #pragma unroll 2
    for (int kb = 0; kb < NT; kb += 8){
        uint2 kk = *(const uint2*)(Kp + (((kb + g)<<2) + c)*2);
        float s0 = 0.f, s1 = 0.f, s2 = 0.f, s3 = 0.f;
        mma_tf32(s0, s1, s2, s3, qa0, qa1, qa2, qa3, kk.x, kk.y);
        float p0 = __expf(s0), p1 = __expf(s1), p2 = __expf(s2), p3 = __expf(s3);
        ls0 += p0 + p1;
        ls1 += p2 + p3;
        // Remap D-fragment (rows g/g+8, cols 2c,2c+1) -> A-fragment (cols c, c+4)
        float q0A = __shfl_sync(0xffffffffu, p0, sA);
        float q1A = __shfl_sync(0xffffffffu, p1, sA);
        float q2A = __shfl_sync(0xffffffffu, p2, sA);
        float q3A = __shfl_sync(0xffffffffu, p3, sA);
        float q0B = __shfl_sync(0xffffffffu, p0, sB);
        float q1B = __shfl_sync(0xffffffffu, p1, sB);
        float q2B = __shfl_sync(0xffffffffu, p2, sB);
        float q3B = __shfl_sync(0xffffffffu, p3, sB);
        u32 pa0 = cvt_tf32(odd ? q1A : q0A);
        u32 pa1 = cvt_tf32(odd ? q3A : q2A);
        u32 pa2 = cvt_tf32(odd ? q1B : q0B);
        u32 pa3 = cvt_tf32(odd ? q3B : q2B);
        uint2 vv = *(const uint2*)(Vt + (((kb >> 3) << 5) + (g << 2) + c)*2);
        mma_tf32(o0, o1, o2, o3, pa0, pa1, pa2, pa3, vv.x, vv.y);
    }

    // denominator: quad-local reduce (lanes of same row-group)
    ls0 += __shfl_xor_sync(0xffffffffu, ls0, 1);
    ls0 += __shfl_xor_sync(0xffffffffu, ls0, 2);
    ls1 += __shfl_xor_sync(0xffffffffu, ls1, 1);
    ls1 += __shfl_xor_sync(0xffffffffu, ls1, 2);
    float inv0 = 1.0f/ls0, inv1 = 1.0f/ls1;

    float* dst0 = g_attn + ((u64)b*NT + qbase + g    )*NE + h*8 + 2*c;
    float* dst1 = g_attn + ((u64)b*NT + qbase + g + 8)*NE + h*8 + 2*c;
    *(float2*)dst0 = make_float2(o0*inv0, o1*inv0);
    *(float2*)dst1 = make_float2(o2*inv1, o3*inv1);
}

// ---- K3: Wo proj + residual + LN1 + qout (R3 version) ----
#define OLN_SMEM ((32*130 + 64*66)*4)
__global__ __launch_bounds__(256) void k_o_ln(
    const float* __restrict__ x, const float* __restrict__ Wo,
    const float* __restrict__ bo, const float* __restrict__ g1,
    const float* __restrict__ be1, const float* __restrict__ th)
{
    extern __shared__ float sm[];
    float* as2 = sm;            // [32][130] dup
    float* Wt  = sm + 32*130;   // [64][66]
    int tid = threadIdx.x;
    int row0 = blockIdx.x*32;
    for (int i = tid; i < 32*64; i += 256){
        int r = i >> 6, c = i & 63;
        float v = g_attn[(u64)(row0 + r)*NE + c];
        *(u64*)(as2 + r*130 + c*2) = pk2(v, v);
    }
    for (int i = tid; i < 4096; i += 256){
        int j = i >> 6, e = i & 63;
        Wt[e*66 + j] = Wo[j*64 + e];
    }
    __syncthreads();
    int j2 = tid & 31, g = tid >> 5;
    int j0 = j2*2;
    u64 acc[4] = {0ull,0ull,0ull,0ull};
    const float* ab = as2 + (g*4)*130;
    #pragma unroll 8
    for (int e = 0; e < 64; ++e){
        u64 w = *(const u64*)(Wt + e*66 + j0);
        acc[0] = ffma2(*(const u64*)(ab +       e*2), w, acc[0]);
        acc[1] = ffma2(*(const u64*)(ab + 130 + e*2), w, acc[1]);
        acc[2] = ffma2(*(const u64*)(ab + 260 + e*2), w, acc[2]);
        acc[3] = ffma2(*(const u64*)(ab + 390 + e*2), w, acc[3]);
    }
    float2 bo2  = *(const float2*)(bo + j0);
    float2 g12  = *(const float2*)(g1 + j0);
    float2 be12 = *(const float2*)(be1 + j0);
    float ct = cosf(*th);
    #pragma unroll
    for (int r = 0; r < 4; ++r){
        int row = row0 + g*4 + r;
        float2 xr = *(const float2*)(x + (u64)row*NE + j0);
        float a0, a1; upk2(a0, a1, acc[r]);
        a0 += bo2.x + xr.x;
        a1 += bo2.y + xr.y;
        float s = a0 + a1;
        #pragma unroll
        for (int o = 16; o > 0; o >>= 1) s += __shfl_xor_sync(0xffffffffu, s, o);
        float mean = s * (1.0f/64.0f);
        float d0 = a0 - mean, d1 = a1 - mean;
        float vs = d0*d0 + d1*d1;
        #pragma unroll
        for (int o = 16; o > 0; o >>= 1) vs += __shfl_xor_sync(0xffffffffu, vs, o);
        float rstd = rsqrtf(vs * (1.0f/64.0f) + 1e-5f);
        float2 y;
        y.x = d0*rstd*g12.x + be12.x;
        y.y = d1*rstd*g12.y + be12.y;
        *(float2*)(g_x1 + (u64)row*NE + j0) = y;
        float2 qo; qo.x = cosf(y.x)*ct; qo.y = cosf(y.y)*ct;
        *(float2*)(g_qout + (u64)row*NE + j0) = qo;
    }
}

// ---- K4: FFN1 relu(qout @ W1^T + b1) (R3 version) ----
#define FFN1_SMEM ((64*260 + 32*130)*4)
__global__ __launch_bounds__(256,2) void k_ffn1(const float* __restrict__ b1)
{
    extern __shared__ float sm[];
    float* Ws  = sm;             // [e][260]
    float* xs2 = sm + 64*260;    // [32][130] dup
    int tid = threadIdx.x;
    int row0 = blockIdx.x*32;
    for (int i = tid; i < 64*64; i += 256){
        int e = i >> 6, q = i & 63;
        *(float4*)(Ws + e*260 + q*4) = *(const float4*)(g_W1t + e*NFF + q*4);
    }
    for (int i = tid; i < 32*64; i += 256){
        int r = i >> 6, c = i & 63;
        float v = g_qout[(u64)(row0 + r)*NE + c];
        *(u64*)(xs2 + r*130 + c*2) = pk2(v, v);
    }
    __syncthreads();
    int cq = tid & 63, rg = tid >> 6;
    u64 acc[8][2];
    #pragma unroll
    for (int i = 0; i < 8; ++i){ acc[i][0] = 0ull; acc[i][1] = 0ull; }
    const float* xb = xs2 + (rg*8)*130;
    #pragma unroll 4
    for (int e = 0; e < 64; ++e){
        u64 w0 = *(const u64*)(Ws + e*260 + cq*2);
        u64 w1 = *(const u64*)(Ws + e*260 + cq*2 + 128);
        #pragma unroll
        for (int i = 0; i < 8; ++i){
            u64 xv = *(const u64*)(xb + i*130 + e*2);
            acc[i][0] = ffma2(xv, w0, acc[i][0]);
            acc[i][1] = ffma2(xv, w1, acc[i][1]);
        }
    }
    int c0 = cq*2;
    float2 ba = *(const float2*)(b1 + c0);
    float2 bb = *(const float2*)(b1 + c0 + 128);
    #pragma unroll
    for (int i = 0; i < 8; ++i){
        int row = row0 + rg*8 + i;
        float a0,a1,a2,a3;
        upk2(a0, a1, acc[i][0]);
        upk2(a2, a3, acc[i][1]);
        float2 o0; o0.x = fmaxf(a0 + ba.x, 0.f); o0.y = fmaxf(a1 + ba.y, 0.f);
        float2 o1; o1.x = fmaxf(a2 + bb.x, 0.f); o1.y = fmaxf(a3 + bb.y, 0.f);
        *(float2*)(g_hid + (u64)row*NFF + c0)       = o0;
        *(float2*)(g_hid + (u64)row*NFF + c0 + 128) = o1;
    }
}

// ---- K5: FFN2 + residual + LN2 -> out (R3 version) ----
#define FFN2_SMEM ((256*66 + 16*514)*4)
__global__ __launch_bounds__(256,2) void k_ffn2(
    const float* __restrict__ b2, const float* __restrict__ g2,
    const float* __restrict__ be2, float* __restrict__ out)
{
    extern __shared__ float sm[];
    float* Ws  = sm;             // [f][66]
    float* hs2 = sm + 256*66;    // [16][514] dup
    int tid = threadIdx.x;
    int row0 = blockIdx.x*16;
    for (int i = tid; i < 256*32; i += 256){
        int f = i >> 5, c2 = i & 31;
        *(float2*)(Ws + f*66 + c2*2) = *(const float2*)(g_W2t + f*NE + c2*2);
    }
    for (int i = tid; i < 16*256; i += 256){
        int r = i >> 8, c = i & 255;
        float v = g_hid[(u64)(row0 + r)*NFF + c];
        *(u64*)(hs2 + r*514 + c*2) = pk2(v, v);
    }
    __syncthreads();
    int cp = tid & 31, ry = tid >> 5;
    int j0 = cp*2;
    u64 acc0 = 0ull, acc1 = 0ull;
    const float* h0p = hs2 + (ry*2)*514;
    const float* h1p = h0p + 514;
    #pragma unroll 8
    for (int f = 0; f < 256; ++f){
        u64 w = *(const u64*)(Ws + f*66 + j0);
        acc0 = ffma2(*(const u64*)(h0p + f*2), w, acc0);
        acc1 = ffma2(*(const u64*)(h1p + f*2), w, acc1);
    }
    float2 b4  = *(const float2*)(b2 + j0);
    float2 g24 = *(const float2*)(g2 + j0);
    float2 be24= *(const float2*)(be2 + j0);
    u64 accs[2] = {acc0, acc1};
    #pragma unroll
    for (int r = 0; r < 2; ++r){
        int row = row0 + ry*2 + r;
        float2 xr = *(const float2*)(g_x1 + (u64)row*NE + j0);
        float a0, a1; upk2(a0, a1, accs[r]);
        a0 += b4.x + xr.x;
        a1 += b4.y + xr.y;
        float s = a0 + a1;
        #pragma unroll
        for (int o = 16; o > 0; o >>= 1) s += __shfl_xor_sync(0xffffffffu, s, o);
        float mean = s * (1.0f/64.0f);
        float d0 = a0 - mean, d1 = a1 - mean;
        float vs = d0*d0 + d1*d1;
        #pragma unroll
        for (int o = 16; o > 0; o >>= 1) vs += __shfl_xor_sync(0xffffffffu, vs, o);
        float rstd = rsqrtf(vs * (1.0f/64.0f) + 1e-5f);
        float2 y;
        y.x = d0*rstd*g24.x + be24.x;
        y.y = d1*rstd*g24.y + be24.y;
        *(float2*)(out + (u64)row*NE + j0) = y;
    }
}

extern "C" void kernel_launch(void* const* d_in, const int* in_sizes, int n_in,
                              void* d_out, int out_size)
{
    const float* x   = (const float*)d_in[0];
    const float* Wq  = (const float*)d_in[1];
    const float* bq  = (const float*)d_in[2];
    const float* Wk  = (const float*)d_in[3];
    const float* bk  = (const float*)d_in[4];
    const float* Wv  = (const float*)d_in[5];
    const float* bv  = (const float*)d_in[6];
    const float* Wo  = (const float*)d_in[7];
    const float* bo  = (const float*)d_in[8];
    const float* tha = (const float*)d_in[9];
    const float* thf = (const float*)d_in[10];
    const float* W1  = (const float*)d_in[11];
    const float* b1  = (const float*)d_in[12];
    const float* W2  = (const float*)d_in[13];
    const float* b2  = (const float*)d_in[14];
    const float* g1  = (const float*)d_in[15];
    const float* be1 = (const float*)d_in[16];
    const float* g2  = (const float*)d_in[17];
    const float* be2 = (const float*)d_in[18];
    float* out = (float*)d_out;

    cudaFuncSetAttribute(k_qkv,  cudaFuncAttributeMaxDynamicSharedMemorySize, QKV_SMEM);
    cudaFuncSetAttribute(k_attn, cudaFuncAttributeMaxDynamicSharedMemorySize, 131072);
    cudaFuncSetAttribute(k_o_ln, cudaFuncAttributeMaxDynamicSharedMemorySize, OLN_SMEM);
    cudaFuncSetAttribute(k_ffn1, cudaFuncAttributeMaxDynamicSharedMemorySize, FFN1_SMEM);
    cudaFuncSetAttribute(k_ffn2, cudaFuncAttributeMaxDynamicSharedMemorySize, FFN2_SMEM);

    k_transpose<<<64, 256>>>(W1, W2);
    k_qkv<<<NROWS/32, 256, QKV_SMEM>>>(x, Wq, bq, Wk, bk, Wv, bv, tha);
    k_attn<<<dim3(8, 64), 512, 131072>>>();
    k_o_ln<<<NROWS/32, 256, OLN_SMEM>>>(x, Wo, bo, g1, be1, thf);
    k_ffn1<<<NROWS/32, 256, FFN1_SMEM>>>(b1);
    k_ffn2<<<NROWS/16, 256, FFN2_SMEM>>>(b2, g2, be2, out);
}

// round 7
// speedup vs baseline: 2.1584x; 1.6563x over previous
#include <cuda_runtime.h>
#include <cuda_fp16.h>
#include <math.h>

#define NB 8
#define NT 2048
#define NE 64
#define NH 8
#define NDK 8
#define NFF 256
#define NROWS (NB*NT)

typedef unsigned long long u64;
typedef unsigned u32;

__device__ __forceinline__ u64 pk2(float x, float y){ u64 r; asm("mov.b64 %0,{%1,%2};":"=l"(r):"f"(x),"f"(y)); return r; }
__device__ __forceinline__ void upk2(float&x,float&y,u64 v){ asm("mov.b64 {%0,%1},%2;":"=f"(x),"=f"(y):"l"(v)); }
__device__ __forceinline__ u64 ffma2(u64 a,u64 b,u64 c){ u64 r; asm("fma.rn.f32x2 %0,%1,%2,%3;":"=l"(r):"l"(a),"l"(b),"l"(c)); return r; }
__device__ __forceinline__ u32 f2h2(float lo, float hi){ u32 r; asm("cvt.rn.f16x2.f32 %0,%1,%2;":"=r"(r):"f"(hi),"f"(lo)); return r; }
__device__ __forceinline__ u32 hadd2u(u32 a, u32 b){ u32 r; asm("add.rn.f16x2 %0,%1,%2;":"=r"(r):"r"(a),"r"(b)); return r; }
__device__ __forceinline__ u32 ex2h2(u32 a){ u32 r; asm("ex2.approx.f16x2 %0,%1;":"=r"(r):"r"(a)); return r; }
__device__ __forceinline__ float2 h2f2(u32 a){
    float lo, hi;
    asm("{.reg .b16 l,h; mov.b32 {l,h},%2; cvt.f32.f16 %0,l; cvt.f32.f16 %1,h;}"
        :"=f"(lo),"=f"(hi):"r"(a));
    return make_float2(lo, hi);
}
#define MMA_F16_K8(c0,c1,c2,c3,a0,a1,b0) \
    asm("mma.sync.aligned.m16n8k8.row.col.f32.f16.f16.f32 " \
        "{%0,%1,%2,%3},{%4,%5},{%6},{%0,%1,%2,%3};" \
        : "+f"(c0),"+f"(c1),"+f"(c2),"+f"(c3) : "r"(a0),"r"(a1),"r"(b0))
#define MMA_F16_K16(c0,c1,c2,c3,a0,a1,a2,a3,b0,b1) \
    asm("mma.sync.aligned.m16n8k16.row.col.f32.f16.f16.f32 " \
        "{%0,%1,%2,%3},{%4,%5,%6,%7},{%8,%9},{%0,%1,%2,%3};" \
        : "+f"(c0),"+f"(c1),"+f"(c2),"+f"(c3) \
        : "r"(a0),"r"(a1),"r"(a2),"r"(a3),"r"(b0),"r"(b1))

// Q scale: 1/sqrt(8) * log2(e)  (exp(s) = 2^(s*log2e), folded into Q)
#define QSCALE 0.5100690827241087f

// ---- scratch ----
// Q/K/V: f16, per-head contiguous [b*8+h][t][8]
__device__ __half g_q[NROWS*NE];
__device__ __half g_k[NROWS*NE];
__device__ __half g_v[NROWS*NE];
__device__ float g_attn[NROWS*NE];   // [b*T+t][64]
__device__ float g_Wqt[NE*NE];       // [e][j] transposed
__device__ float g_Wkt[NE*NE];
__device__ float g_Wvt[NE*NE];
__device__ float g_Wot[NE*NE];
__device__ float g_W1t[NE*NFF];      // [e][f]
__device__ float g_W2t[NFF*NE];      // [f][j]

__global__ void k_transpose(const float* __restrict__ W1, const float* __restrict__ W2,
                            const float* __restrict__ Wq, const float* __restrict__ Wk,
                            const float* __restrict__ Wv, const float* __restrict__ Wo){
    int i = blockIdx.x*256 + threadIdx.x;
    if (i < NE*NFF){
        int e = i / NFF, f = i % NFF;
        g_W1t[i] = W1[f*NE + e];
        int f2 = i / NE, j = i % NE;
        g_W2t[i] = W2[j*NFF + f2];
    }
    if (i < NE*NE){
        int e = i >> 6, j = i & 63;
        g_Wqt[i] = Wq[j*NE + e];
        g_Wkt[i] = Wk[j*NE + e];
        g_Wvt[i] = Wv[j*NE + e];
        g_Wot[i] = Wo[j*NE + e];
    }
}

// ---- K1: QKV merged + cos(.+theta), f16 per-head outputs ----
#define QKV_SMEM ((32*130 + 3*64*68)*4)
__global__ __launch_bounds__(256) void k_qkv(
    const float* __restrict__ x,
    const float* __restrict__ bq, const float* __restrict__ bk,
    const float* __restrict__ bv, const float* __restrict__ th)
{
    extern __shared__ float sm[];
    float* xs2 = sm;            // [32][130] duplicated pairs
    float* Wt  = sm + 32*130;   // [3][64][68]
    int tid = threadIdx.x;
    int row0 = blockIdx.x*32;
    int b = row0 >> 11, t0 = row0 & (NT-1);

    for (int i = tid; i < 32*64; i += 256){
        int r = i >> 6, c = i & 63;
        float v = x[(u64)(row0 + r)*NE + c];
        *(u64*)(xs2 + r*130 + c*2) = pk2(v, v);
    }
    // coalesced float4 fills from pre-transposed weights
    for (int i = tid; i < 3072; i += 256){
        int m = i >> 10, rem = i & 1023;
        int e = rem >> 4, q = rem & 15;
        const float* src = (m == 0) ? g_Wqt : (m == 1) ? g_Wkt : g_Wvt;
        *(float4*)(Wt + m*4352 + e*68 + q*4) = *(const float4*)(src + e*64 + q*4);
    }
    __syncthreads();

    const float theta = *th;
    int j2 = tid & 31, g = tid >> 5;
    int j0 = j2*2;
    int h = j0 >> 3, d0 = j0 & 7;
    u64 aq[4] = {0,0,0,0}, ak[4] = {0,0,0,0}, av[4] = {0,0,0,0};
    const float* xb = xs2 + (g*4)*130;
    #pragma unroll 4
    for (int e = 0; e < 64; ++e){
        u64 wq = *(const u64*)(Wt +        e*68 + j0);
        u64 wk = *(const u64*)(Wt + 4352 + e*68 + j0);
        u64 wv = *(const u64*)(Wt + 8704 + e*68 + j0);
        #pragma unroll
        for (int r = 0; r < 4; ++r){
            u64 xv = *(const u64*)(xb + r*130 + e*2);
            aq[r] = ffma2(xv, wq, aq[r]);
            ak[r] = ffma2(xv, wk, ak[r]);
            av[r] = ffma2(xv, wv, av[r]);
        }
    }
    float2 b_q = *(const float2*)(bq + j0);
    float2 b_k = *(const float2*)(bk + j0);
    float2 b_v = *(const float2*)(bv + j0);
    u32* qdst = (u32*)g_q;
    u32* kdst = (u32*)g_k;
    u32* vdst = (u32*)g_v;
    #pragma unroll
    for (int r = 0; r < 4; ++r){
        int t = t0 + g*4 + r;
        u64 idx = ((u64)(b*NH + h)*NT + t)*4 + (d0 >> 1);
        float a0, a1;
        upk2(a0, a1, aq[r]);
        qdst[idx] = f2h2(cosf(a0 + b_q.x + theta)*QSCALE, cosf(a1 + b_q.y + theta)*QSCALE);
        upk2(a0, a1, ak[r]);
        kdst[idx] = f2h2(cosf(a0 + b_k.x + theta), cosf(a1 + b_k.y + theta));
        upk2(a0, a1, av[r]);
        vdst[idx] = f2h2(cosf(a0 + b_v.x + theta), cosf(a1 + b_v.y + theta));
    }
}

// ---- K2: f16 flash attention, no shuffles, ex2.f16x2 softmax ----
// 512 thr = 16 warps x 16 queries = 256 q/block; grid (8, 64).
// Smem: Kh 32KB + Vraw 32KB + Vh 32KB = 96KB -> 2 blocks/SM.
#define ATTN_SMEM (96*1024)
__global__ void __launch_bounds__(512,2) k_attn()
{
    extern __shared__ u32 smu[];
    u32*   Kh   = smu;            // Kh[t*4+c] = half2(K[t][2c],K[t][2c+1])
    u32*   Vraw = smu + 8192;     // raw V rows
    uint2* Vh   = (uint2*)(smu + 16384);  // Vh[(m*8+d)*4+c] = B-frag pairs
    int bh = blockIdx.y;
    int tid = threadIdx.x;
    const u32* kg = (const u32*)(g_k + (u64)bh*NT*NDK);
    const u32* vg = (const u32*)(g_v + (u64)bh*NT*NDK);
    for (int i = tid; i < 8192; i += 512){ Kh[i] = kg[i]; Vraw[i] = vg[i]; }
    __syncthreads();
    const unsigned short* vb = (const unsigned short*)Vraw;
    for (int j = tid; j < 4096; j += 512){
        int m = j >> 5, d = (j >> 2) & 7, c = j & 3;
        u32 lo = (u32)vb[(16*m + 2*c    )*8 + d] | ((u32)vb[(16*m + 2*c + 1)*8 + d] << 16);
        u32 hi = (u32)vb[(16*m + 2*c + 8)*8 + d] | ((u32)vb[(16*m + 2*c + 9)*8 + d] << 16);
        Vh[j] = make_uint2(lo, hi);   // j == (m*8+d)*4+c
    }
    __syncthreads();

    int wid = tid >> 5, lane = tid & 31;
    int g = lane >> 2, c = lane & 3;
    int qbase = blockIdx.x*256 + wid*16;
    int b = bh >> 3, h = bh & 7;

    const u32* qg = (const u32*)(g_q + (u64)bh*NT*NDK);
    u32 qa0 = qg[(qbase + g    )*4 + c];   // A-frag: row g,   k=2c,2c+1
    u32 qa1 = qg[(qbase + g + 8)*4 + c];   //         row g+8

    float o0 = 0.f, o1 = 0.f, o2 = 0.f, o3 = 0.f;
    float ls0 = 0.f, ls1 = 0.f;
    const u32*   KpW = Kh + g*4 + c;
    const uint2* VpW = Vh + g*4 + c;

    for (int mg = 0; mg < 32; ++mg){
        u32 hacc0 = 0u, hacc1 = 0u;
        #pragma unroll
        for (int mi = 0; mi < 4; ++mi){
            int m = mg*4 + mi;
            u32 kb0 = KpW[m*64];
            u32 kb1 = KpW[m*64 + 32];
            float s0=0.f,s1=0.f,s2=0.f,s3=0.f;
            MMA_F16_K8(s0,s1,s2,s3, qa0,qa1, kb0);
            float t0=0.f,t1=0.f,t2=0.f,t3=0.f;
            MMA_F16_K8(t0,t1,t2,t3, qa0,qa1, kb1);
            u32 ra0 = ex2h2(f2h2(s0, s1));   // row g,   k 2c,2c+1
            u32 ra1 = ex2h2(f2h2(s2, s3));   // row g+8, k 2c,2c+1
            u32 ra2 = ex2h2(f2h2(t0, t1));   // row g,   k 2c+8,2c+9
            u32 ra3 = ex2h2(f2h2(t2, t3));   // row g+8
            hacc0 = hadd2u(hacc0, hadd2u(ra0, ra2));
            hacc1 = hadd2u(hacc1, hadd2u(ra1, ra3));
            uint2 vv = VpW[m*32];
            MMA_F16_K16(o0,o1,o2,o3, ra0,ra1,ra2,ra3, vv.x, vv.y);
        }
        float2 f0 = h2f2(hacc0); ls0 += f0.x + f0.y;
        float2 f1 = h2f2(hacc1); ls1 += f1.x + f1.y;
    }

    // denominator: reduce over the 4 c-lanes of each row group
    ls0 += __shfl_xor_sync(0xffffffffu, ls0, 1);
    ls0 += __shfl_xor_sync(0xffffffffu, ls0, 2);
    ls1 += __shfl_xor_sync(0xffffffffu, ls1, 1);
    ls1 += __shfl_xor_sync(0xffffffffu, ls1, 2);
    float inv0 = 1.0f/ls0, inv1 = 1.0f/ls1;

    float* dst0 = g_attn + ((u64)b*NT + qbase + g    )*NE + h*8 + 2*c;
    float* dst1 = g_attn + ((u64)b*NT + qbase + g + 8)*NE + h*8 + 2*c;
    *(float2*)dst0 = make_float2(o0*inv0, o1*inv0);
    *(float2*)dst1 = make_float2(o2*inv1, o3*inv1);
}

// ---- K3: fully fused tail. All weights smem-resident (204KB, 1 block/SM).
// 512 threads, 32 rows/block, grid 512.
#define TAIL_SMEM ((64*64 + 64*260 + 256*66 + 32*65 + 32*65 + 32*258 + 32*64)*4)
__global__ __launch_bounds__(512) void k_tail(
    const float* __restrict__ x,  const float* __restrict__ bo,
    const float* __restrict__ g1, const float* __restrict__ be1,
    const float* __restrict__ thf,
    const float* __restrict__ b1, const float* __restrict__ b2,
    const float* __restrict__ g2, const float* __restrict__ be2,
    float* __restrict__ out)
{
    extern __shared__ float sm[];
    float* Wot = sm;                 // [64][64]
    float* W1t = Wot + 4096;         // [64][260]
    float* W2t = W1t + 64*260;       // [256][66]
    float* as_ = W2t + 256*66;       // [32][65]
    float* qs  = as_ + 32*65;        // [32][65]
    float* hs  = qs  + 32*65;        // [32][258]
    float* x1s = hs  + 32*258;       // [32][64]
    int tid = threadIdx.x;
    int row0 = blockIdx.x*32;

    for (int i = tid; i < 1024; i += 512)
        *(float4*)(Wot + i*4) = *(const float4*)(g_Wot + i*4);
    for (int i = tid; i < 4096; i += 512){
        int e = i >> 6, q = i & 63;
        *(float4*)(W1t + e*260 + q*4) = *(const float4*)(g_W1t + e*NFF + q*4);
    }
    for (int i = tid; i < 8192; i += 512){
        int f = i >> 5, q = i & 31;
        *(float2*)(W2t + f*66 + q*2) = *(const float2*)(g_W2t + f*NE + q*2);
    }
    for (int i = tid; i < 2048; i += 512){
        int r = i >> 6, col = i & 63;
        as_[r*65 + col] = g_attn[(u64)(row0 + r)*NE + col];
    }
    __syncthreads();

    // Stage A: Wo proj + residual + LN1 + qout. thread = 2 rows x 2 cols.
    {
        int ry = tid >> 5;           // 0..15 -> rows 2ry, 2ry+1
        int j0 = (tid & 31)*2;
        float a00=0.f,a01=0.f,a10=0.f,a11=0.f;
        #pragma unroll 8
        for (int e = 0; e < 64; ++e){
            float2 w = *(float2*)(Wot + e*64 + j0);
            float xa = as_[(2*ry    )*65 + e];
            float xb2 = as_[(2*ry + 1)*65 + e];
            a00 = fmaf(xa,  w.x, a00); a01 = fmaf(xa,  w.y, a01);
            a10 = fmaf(xb2, w.x, a10); a11 = fmaf(xb2, w.y, a11);
        }
        float2 bo2  = *(const float2*)(bo  + j0);
        float2 g12  = *(const float2*)(g1  + j0);
        float2 be12 = *(const float2*)(be1 + j0);
        float ct = cosf(*thf);
        float ar[2][2] = {{a00,a01},{a10,a11}};
        #pragma unroll
        for (int rr = 0; rr < 2; ++rr){
            int r = 2*ry + rr;
            float2 xr = *(const float2*)(x + (u64)(row0 + r)*NE + j0);
            float a0 = ar[rr][0] + bo2.x + xr.x;
            float a1 = ar[rr][1] + bo2.y + xr.y;
            float s = a0 + a1;
            #pragma unroll
            for (int o = 16; o > 0; o >>= 1) s += __shfl_xor_sync(0xffffffffu, s, o);
            float mean = s * (1.0f/64.0f);
            float d0 = a0 - mean, d1 = a1 - mean;
            float vs = d0*d0 + d1*d1;
            #pragma unroll
            for (int o = 16; o > 0; o >>= 1) vs += __shfl_xor_sync(0xffffffffu, vs, o);
            float rstd = rsqrtf(vs * (1.0f/64.0f) + 1e-5f);
            float y0 = d0*rstd*g12.x + be12.x;
            float y1 = d1*rstd*g12.y + be12.y;
            *(float2*)(x1s + r*64 + j0) = make_float2(y0, y1);
            qs[r*65 + j0]     = cosf(y0)*ct;
            qs[r*65 + j0 + 1] = cosf(y1)*ct;
        }
    }
    __syncthreads();

    // Stage B: FFN1 relu. thread = 4 rows x 2 colpairs (c0, c0+128).
    {
        int rb = (tid >> 6)*4;       // 0..28
        int cq = tid & 63;
        int c0 = cq*2;
        u64 acc[4][2];
        #pragma unroll
        for (int i = 0; i < 4; ++i){ acc[i][0] = 0ull; acc[i][1] = 0ull; }
        #pragma unroll 4
        for (int e = 0; e < 64; ++e){
            u64 w0 = *(const u64*)(W1t + e*260 + c0);
            u64 w1 = *(const u64*)(W1t + e*260 + c0 + 128);
            #pragma unroll
            for (int i = 0; i < 4; ++i){
                float qv = qs[(rb + i)*65 + e];
                u64 q2v = pk2(qv, qv);
                acc[i][0] = ffma2(q2v, w0, acc[i][0]);
                acc[i][1] = ffma2(q2v, w1, acc[i][1]);
            }
        }
        float2 ba = *(const float2*)(b1 + c0);
        float2 bb = *(const float2*)(b1 + c0 + 128);
        #pragma unroll
        for (int i = 0; i < 4; ++i){
            float a0,a1,a2,a3;
            upk2(a0, a1, acc[i][0]);
            upk2(a2, a3, acc[i][1]);
            *(float2*)(hs + (rb+i)*258 + c0) =
                make_float2(fmaxf(a0 + ba.x, 0.f), fmaxf(a1 + ba.y, 0.f));
            *(float2*)(hs + (rb+i)*258 + c0 + 128) =
                make_float2(fmaxf(a2 + bb.x, 0.f), fmaxf(a3 + bb.y, 0.f));
        }
    }
    __syncthreads();

    // Stage C: FFN2 + residual + LN2. thread = 1 row x 2 colpairs (j0, j0+32).
    {
        int rr = tid >> 4;           // 0..31
        int j0 = (tid & 15)*2;
        u64 accA = 0ull, accB = 0ull;
        #pragma unroll 8
        for (int f = 0; f < 256; ++f){
            float hv = hs[rr*258 + f];
            u64 h2v = pk2(hv, hv);
            accA = ffma2(h2v, *(const u64*)(W2t + f*66 + j0),      accA);
            accB = ffma2(h2v, *(const u64*)(W2t + f*66 + j0 + 32), accB);
        }
        float a0,a1,a2,a3;
        upk2(a0, a1, accA);
        upk2(a2, a3, accB);
        float2 b2a  = *(const float2*)(b2  + j0);
        float2 b2b  = *(const float2*)(b2  + j0 + 32);
        float2 g2a  = *(const float2*)(g2  + j0);
        float2 g2b  = *(const float2*)(g2  + j0 + 32);
        float2 be2a = *(const float2*)(be2 + j0);
        float2 be2b = *(const float2*)(be2 + j0 + 32);
        float2 x1a = *(float2*)(x1s + rr*64 + j0);
        float2 x1b = *(float2*)(x1s + rr*64 + j0 + 32);
        a0 += b2a.x + x1a.x;  a1 += b2a.y + x1a.y;
        a2 += b2b.x + x1b.x;  a3 += b2b.y + x1b.y;
        float s = a0 + a1 + a2 + a3;
        #pragma unroll
        for (int o = 8; o > 0; o >>= 1) s += __shfl_xor_sync(0xffffffffu, s, o);
        float mean = s * (1.0f/64.0f);
        float d0 = a0 - mean, d1 = a1 - mean, d2 = a2 - mean, d3 = a3 - mean;
        float vs = d0*d0 + d1*d1 + d2*d2 + d3*d3;
        #pragma unroll
        for (int o = 8; o > 0; o >>= 1) vs += __shfl_xor_sync(0xffffffffu, vs, o);
        float rstd = rsqrtf(vs * (1.0f/64.0f) + 1e-5f);
        int row = row0 + rr;
        *(float2*)(out + (u64)row*NE + j0) =
            make_float2(d0*rstd*g2a.x + be2a.x, d1*rstd*g2a.y + be2a.y);
        *(float2*)(out + (u64)row*NE + j0 + 32) =
            make_float2(d2*rstd*g2b.x + be2b.x, d3*rstd*g2b.y + be2b.y);
    }
}

extern "C" void kernel_launch(void* const* d_in, const int* in_sizes, int n_in,
                              void* d_out, int out_size)
{
    const float* x   = (const float*)d_in[0];
    const float* Wq  = (const float*)d_in[1];
    const float* bq  = (const float*)d_in[2];
    const float* Wk  = (const float*)d_in[3];
    const float* bk  = (const float*)d_in[4];
    const float* Wv  = (const float*)d_in[5];
    const float* bv  = (const float*)d_in[6];
    const float* Wo  = (const float*)d_in[7];
    const float* bo  = (const float*)d_in[8];
    const float* tha = (const float*)d_in[9];
    const float* thf = (const float*)d_in[10];
    const float* W1  = (const float*)d_in[11];
    const float* b1  = (const float*)d_in[12];
    const float* W2  = (const float*)d_in[13];
    const float* b2  = (const float*)d_in[14];
    const float* g1  = (const float*)d_in[15];
    const float* be1 = (const float*)d_in[16];
    const float* g2  = (const float*)d_in[17];
    const float* be2 = (const float*)d_in[18];
    float* out = (float*)d_out;

    cudaFuncSetAttribute(k_qkv,  cudaFuncAttributeMaxDynamicSharedMemorySize, QKV_SMEM);
    cudaFuncSetAttribute(k_attn, cudaFuncAttributeMaxDynamicSharedMemorySize, ATTN_SMEM);
    cudaFuncSetAttribute(k_tail, cudaFuncAttributeMaxDynamicSharedMemorySize, TAIL_SMEM);

    k_transpose<<<64, 256>>>(W1, W2, Wq, Wk, Wv, Wo);
    k_qkv<<<NROWS/32, 256, QKV_SMEM>>>(x, bq, bk, bv, tha);
    k_attn<<<dim3(8, 64), 512, ATTN_SMEM>>>();
    k_tail<<<NROWS/32, 512, TAIL_SMEM>>>(x, bo, g1, be1, thf, b1, b2, g2, be2, out);
}

// round 8
// speedup vs baseline: 3.4317x; 1.5899x over previous
#include <cuda_runtime.h>
#include <cuda_fp16.h>
#include <math.h>

#define NB 8
#define NT 2048
#define NE 64
#define NH 8
#define NDK 8
#define NFF 256
#define NROWS (NB*NT)

typedef unsigned long long u64;
typedef unsigned u32;

__device__ __forceinline__ u64 pk2(float x, float y){ u64 r; asm("mov.b64 %0,{%1,%2};":"=l"(r):"f"(x),"f"(y)); return r; }
__device__ __forceinline__ void upk2(float&x,float&y,u64 v){ asm("mov.b64 {%0,%1},%2;":"=f"(x),"=f"(y):"l"(v)); }
__device__ __forceinline__ u64 ffma2(u64 a,u64 b,u64 c){ u64 r; asm("fma.rn.f32x2 %0,%1,%2,%3;":"=l"(r):"l"(a),"l"(b),"l"(c)); return r; }
__device__ __forceinline__ u32 f2h2(float lo, float hi){ u32 r; asm("cvt.rn.f16x2.f32 %0,%1,%2;":"=r"(r):"f"(hi),"f"(lo)); return r; }
__device__ __forceinline__ u32 hadd2u(u32 a, u32 b){ u32 r; asm("add.rn.f16x2 %0,%1,%2;":"=r"(r):"r"(a),"r"(b)); return r; }
__device__ __forceinline__ u32 ex2h2(u32 a){ u32 r; asm("ex2.approx.f16x2 %0,%1;":"=r"(r):"r"(a)); return r; }
__device__ __forceinline__ float2 h2f2(u32 a){
    float lo, hi;
    asm("{.reg .b16 l,h; mov.b32 {l,h},%2; cvt.f32.f16 %0,l; cvt.f32.f16 %1,h;}"
        :"=f"(lo),"=f"(hi):"r"(a));
    return make_float2(lo, hi);
}
#define MMA_F16_K8(c0,c1,c2,c3,a0,a1,b0) \
    asm("mma.sync.aligned.m16n8k8.row.col.f32.f16.f16.f32 " \
        "{%0,%1,%2,%3},{%4,%5},{%6},{%0,%1,%2,%3};" \
        : "+f"(c0),"+f"(c1),"+f"(c2),"+f"(c3) : "r"(a0),"r"(a1),"r"(b0))
#define MMA_F16_K16(c0,c1,c2,c3,a0,a1,a2,a3,b0,b1) \
    asm("mma.sync.aligned.m16n8k16.row.col.f32.f16.f16.f32 " \
        "{%0,%1,%2,%3},{%4,%5,%6,%7},{%8,%9},{%0,%1,%2,%3};" \
        : "+f"(c0),"+f"(c1),"+f"(c2),"+f"(c3) \
        : "r"(a0),"r"(a1),"r"(a2),"r"(a3),"r"(b0),"r"(b1))

// Q scale: 1/sqrt(8) * log2(e)
#define QSCALE 0.5100690827241087f

// ---- scratch ----
__device__ __half g_q[NROWS*NE];     // per-head [b*8+h][t][8]
__device__ __half g_k[NROWS*NE];
__device__ __half g_v[NROWS*NE];
__device__ __half g_attn[NROWS*NE];  // row-major [b*T+t][64], f16
__device__ float g_Wqt[NE*NE];       // [e][j] fp32 transposed (for qkv)
__device__ float g_Wkt[NE*NE];
__device__ float g_Wvt[NE*NE];
__device__ __half g_WoH[NE*NE];      // [j][e] f16, original layout = B-frag [n][k]
__device__ __half g_W1H[NFF*NE];     // [f][e]
__device__ __half g_W2H[NE*NFF];     // [j][f]

__global__ void k_transpose(const float* __restrict__ W1, const float* __restrict__ W2,
                            const float* __restrict__ Wq, const float* __restrict__ Wk,
                            const float* __restrict__ Wv, const float* __restrict__ Wo){
    int i = blockIdx.x*256 + threadIdx.x;
    if (i < NE*NFF){
        g_W1H[i] = __float2half(W1[i]);
        g_W2H[i] = __float2half(W2[i]);
    }
    if (i < NE*NE){
        int e = i >> 6, j = i & 63;
        g_Wqt[i] = Wq[j*NE + e];
        g_Wkt[i] = Wk[j*NE + e];
        g_Wvt[i] = Wv[j*NE + e];
        g_WoH[i] = __float2half(Wo[i]);
    }
}

// ---- K1: QKV merged + cos(.+theta), f16 per-head outputs ----
#define QKV_SMEM ((32*130 + 3*64*68)*4)
__global__ __launch_bounds__(256) void k_qkv(
    const float* __restrict__ x,
    const float* __restrict__ bq, const float* __restrict__ bk,
    const float* __restrict__ bv, const float* __restrict__ th)
{
    extern __shared__ float sm[];
    float* xs2 = sm;            // [32][130] duplicated pairs
    float* Wt  = sm + 32*130;   // [3][64][68]
    int tid = threadIdx.x;
    int row0 = blockIdx.x*32;
    int b = row0 >> 11, t0 = row0 & (NT-1);

    for (int i = tid; i < 32*64; i += 256){
        int r = i >> 6, c = i & 63;
        float v = x[(u64)(row0 + r)*NE + c];
        *(u64*)(xs2 + r*130 + c*2) = pk2(v, v);
    }
    for (int i = tid; i < 3072; i += 256){
        int m = i >> 10, rem = i & 1023;
        int e = rem >> 4, q = rem & 15;
        const float* src = (m == 0) ? g_Wqt : (m == 1) ? g_Wkt : g_Wvt;
        *(float4*)(Wt + m*4352 + e*68 + q*4) = *(const float4*)(src + e*64 + q*4);
    }
    __syncthreads();

    const float theta = *th;
    int j2 = tid & 31, g = tid >> 5;
    int j0 = j2*2;
    int h = j0 >> 3, d0 = j0 & 7;
    u64 aq[4] = {0,0,0,0}, ak[4] = {0,0,0,0}, av[4] = {0,0,0,0};
    const float* xb = xs2 + (g*4)*130;
    #pragma unroll 4
    for (int e = 0; e < 64; ++e){
        u64 wq = *(const u64*)(Wt +        e*68 + j0);
        u64 wk = *(const u64*)(Wt + 4352 + e*68 + j0);
        u64 wv = *(const u64*)(Wt + 8704 + e*68 + j0);
        #pragma unroll
        for (int r = 0; r < 4; ++r){
            u64 xv = *(const u64*)(xb + r*130 + e*2);
            aq[r] = ffma2(xv, wq, aq[r]);
            ak[r] = ffma2(xv, wk, ak[r]);
            av[r] = ffma2(xv, wv, av[r]);
        }
    }
    float2 b_q = *(const float2*)(bq + j0);
    float2 b_k = *(const float2*)(bk + j0);
    float2 b_v = *(const float2*)(bv + j0);
    u32* qdst = (u32*)g_q;
    u32* kdst = (u32*)g_k;
    u32* vdst = (u32*)g_v;
    #pragma unroll
    for (int r = 0; r < 4; ++r){
        int t = t0 + g*4 + r;
        u64 idx = ((u64)(b*NH + h)*NT + t)*4 + (d0 >> 1);
        float a0, a1;
        upk2(a0, a1, aq[r]);
        qdst[idx] = f2h2(cosf(a0 + b_q.x + theta)*QSCALE, cosf(a1 + b_q.y + theta)*QSCALE);
        upk2(a0, a1, ak[r]);
        kdst[idx] = f2h2(cosf(a0 + b_k.x + theta), cosf(a1 + b_k.y + theta));
        upk2(a0, a1, av[r]);
        vdst[idx] = f2h2(cosf(a0 + b_v.x + theta), cosf(a1 + b_v.y + theta));
    }
}

// ---- K2: f16 flash attention, f16 output ----
#define ATTN_SMEM (96*1024)
__global__ void __launch_bounds__(512,2) k_attn()
{
    extern __shared__ u32 smu[];
    u32*   Kh   = smu;
    u32*   Vraw = smu + 8192;
    uint2* Vh   = (uint2*)(smu + 16384);
    int bh = blockIdx.y;
    int tid = threadIdx.x;
    const u32* kg = (const u32*)(g_k + (u64)bh*NT*NDK);
    const u32* vg = (const u32*)(g_v + (u64)bh*NT*NDK);
    for (int i = tid; i < 8192; i += 512){ Kh[i] = kg[i]; Vraw[i] = vg[i]; }
    __syncthreads();
    const unsigned short* vb = (const unsigned short*)Vraw;
    for (int j = tid; j < 4096; j += 512){
        int m = j >> 5, d = (j >> 2) & 7, c = j & 3;
        u32 lo = (u32)vb[(16*m + 2*c    )*8 + d] | ((u32)vb[(16*m + 2*c + 1)*8 + d] << 16);
        u32 hi = (u32)vb[(16*m + 2*c + 8)*8 + d] | ((u32)vb[(16*m + 2*c + 9)*8 + d] << 16);
        Vh[j] = make_uint2(lo, hi);
    }
    __syncthreads();

    int wid = tid >> 5, lane = tid & 31;
    int g = lane >> 2, c = lane & 3;
    int qbase = blockIdx.x*256 + wid*16;
    int b = bh >> 3, h = bh & 7;

    const u32* qg = (const u32*)(g_q + (u64)bh*NT*NDK);
    u32 qa0 = qg[(qbase + g    )*4 + c];
    u32 qa1 = qg[(qbase + g + 8)*4 + c];

    float o0 = 0.f, o1 = 0.f, o2 = 0.f, o3 = 0.f;
    float ls0 = 0.f, ls1 = 0.f;
    const u32*   KpW = Kh + g*4 + c;
    const uint2* VpW = Vh + g*4 + c;

    for (int mg = 0; mg < 32; ++mg){
        u32 hacc0 = 0u, hacc1 = 0u;
        #pragma unroll
        for (int mi = 0; mi < 4; ++mi){
            int m = mg*4 + mi;
            u32 kb0 = KpW[m*64];
            u32 kb1 = KpW[m*64 + 32];
            float s0=0.f,s1=0.f,s2=0.f,s3=0.f;
            MMA_F16_K8(s0,s1,s2,s3, qa0,qa1, kb0);
            float t0=0.f,t1=0.f,t2=0.f,t3=0.f;
            MMA_F16_K8(t0,t1,t2,t3, qa0,qa1, kb1);
            u32 ra0 = ex2h2(f2h2(s0, s1));
            u32 ra1 = ex2h2(f2h2(s2, s3));
            u32 ra2 = ex2h2(f2h2(t0, t1));
            u32 ra3 = ex2h2(f2h2(t2, t3));
            hacc0 = hadd2u(hacc0, hadd2u(ra0, ra2));
            hacc1 = hadd2u(hacc1, hadd2u(ra1, ra3));
            uint2 vv = VpW[m*32];
            MMA_F16_K16(o0,o1,o2,o3, ra0,ra1,ra2,ra3, vv.x, vv.y);
        }
        float2 f0 = h2f2(hacc0); ls0 += f0.x + f0.y;
        float2 f1 = h2f2(hacc1); ls1 += f1.x + f1.y;
    }

    ls0 += __shfl_xor_sync(0xffffffffu, ls0, 1);
    ls0 += __shfl_xor_sync(0xffffffffu, ls0, 2);
    ls1 += __shfl_xor_sync(0xffffffffu, ls1, 1);
    ls1 += __shfl_xor_sync(0xffffffffu, ls1, 2);
    float inv0 = 1.0f/ls0, inv1 = 1.0f/ls1;

    u32* dstw = (u32*)g_attn;
    dstw[((u64)b*NT + qbase + g    )*32 + h*4 + c] = f2h2(o0*inv0, o1*inv0);
    dstw[((u64)b*NT + qbase + g + 8)*32 + h*4 + c] = f2h2(o2*inv1, o3*inv1);
}

// ---- K3: tensor-core fused tail, zero smem ----
// Warp = 16 rows. Block = 128 thr (4 warps, 64 rows). Grid 256.
// Stage A: attn(f16) @ WoH -> +bo +x -> LN1 -> x1 (fp32 regs) -> cos*ct -> A-frag
// Stage B: @ W1H -> +b1 -> relu -> A-frag (register-pure)
// Stage C: @ W2H -> +b2 +x1 -> LN2 -> out
__global__ __launch_bounds__(128) void k_tail(
    const float* __restrict__ x,  const float* __restrict__ bo,
    const float* __restrict__ g1, const float* __restrict__ be1,
    const float* __restrict__ thf,
    const float* __restrict__ b1, const float* __restrict__ b2,
    const float* __restrict__ g2, const float* __restrict__ be2,
    float* __restrict__ out)
{
    int warp = threadIdx.x >> 5, lane = threadIdx.x & 31;
    int g = lane >> 2, c = lane & 3;
    int r0 = blockIdx.x*64 + warp*16;

    // ---- Stage A ----
    const u32* attnW = (const u32*)g_attn;
    u32 qa[4][4];
    #pragma unroll
    for (int u = 0; u < 4; ++u){
        qa[u][0] = attnW[(u64)(r0 + g    )*32 + 8*u + c];
        qa[u][1] = attnW[(u64)(r0 + g + 8)*32 + 8*u + c];
        qa[u][2] = attnW[(u64)(r0 + g    )*32 + 8*u + c + 4];
        qa[u][3] = attnW[(u64)(r0 + g + 8)*32 + 8*u + c + 4];
    }
    const u32* WoW = (const u32*)g_WoH;
    float da[8][4];
    #pragma unroll
    for (int nb = 0; nb < 8; ++nb){
        float d0=0.f,d1=0.f,d2=0.f,d3=0.f;
        #pragma unroll
        for (int u = 0; u < 4; ++u){
            u32 wb0 = WoW[(8*nb + g)*32 + 8*u + c];
            u32 wb1 = WoW[(8*nb + g)*32 + 8*u + c + 4];
            MMA_F16_K16(d0,d1,d2,d3, qa[u][0],qa[u][1],qa[u][2],qa[u][3], wb0,wb1);
        }
        float2 bo2 = *(const float2*)(bo + 8*nb + 2*c);
        float2 xg = *(const float2*)(x + (u64)(r0 + g    )*NE + 8*nb + 2*c);
        float2 xh = *(const float2*)(x + (u64)(r0 + g + 8)*NE + 8*nb + 2*c);
        da[nb][0] = d0 + bo2.x + xg.x;
        da[nb][1] = d1 + bo2.y + xg.y;
        da[nb][2] = d2 + bo2.x + xh.x;
        da[nb][3] = d3 + bo2.y + xh.y;
    }
    // LN1 (rows g and g+8)
    float sg = 0.f, sh = 0.f;
    #pragma unroll
    for (int nb = 0; nb < 8; ++nb){ sg += da[nb][0] + da[nb][1]; sh += da[nb][2] + da[nb][3]; }
    sg += __shfl_xor_sync(0xffffffffu, sg, 1);
    sg += __shfl_xor_sync(0xffffffffu, sg, 2);
    sh += __shfl_xor_sync(0xffffffffu, sh, 1);
    sh += __shfl_xor_sync(0xffffffffu, sh, 2);
    float mg_ = sg*(1.0f/64.0f), mh_ = sh*(1.0f/64.0f);
    float vg_ = 0.f, vh_ = 0.f;
    #pragma unroll
    for (int nb = 0; nb < 8; ++nb){
        da[nb][0] -= mg_; da[nb][1] -= mg_;
        da[nb][2] -= mh_; da[nb][3] -= mh_;
        vg_ += da[nb][0]*da[nb][0] + da[nb][1]*da[nb][1];
        vh_ += da[nb][2]*da[nb][2] + da[nb][3]*da[nb][3];
    }
    vg_ += __shfl_xor_sync(0xffffffffu, vg_, 1);
    vg_ += __shfl_xor_sync(0xffffffffu, vg_, 2);
    vh_ += __shfl_xor_sync(0xffffffffu, vh_, 1);
    vh_ += __shfl_xor_sync(0xffffffffu, vh_, 2);
    float rg_ = rsqrtf(vg_*(1.0f/64.0f) + 1e-5f);
    float rh_ = rsqrtf(vh_*(1.0f/64.0f) + 1e-5f);
    float ct = cosf(*thf);
    float x1g[16], x1h[16];
    u32 pa[4][4];
    #pragma unroll
    for (int nb = 0; nb < 8; ++nb){
        float2 g12  = *(const float2*)(g1  + 8*nb + 2*c);
        float2 be12 = *(const float2*)(be1 + 8*nb + 2*c);
        x1g[2*nb]   = da[nb][0]*rg_*g12.x + be12.x;
        x1g[2*nb+1] = da[nb][1]*rg_*g12.y + be12.y;
        x1h[2*nb]   = da[nb][2]*rh_*g12.x + be12.x;
        x1h[2*nb+1] = da[nb][3]*rh_*g12.y + be12.y;
    }
    #pragma unroll
    for (int u = 0; u < 4; ++u){
        pa[u][0] = f2h2(cosf(x1g[4*u    ])*ct, cosf(x1g[4*u + 1])*ct);
        pa[u][1] = f2h2(cosf(x1h[4*u    ])*ct, cosf(x1h[4*u + 1])*ct);
        pa[u][2] = f2h2(cosf(x1g[4*u + 2])*ct, cosf(x1g[4*u + 3])*ct);
        pa[u][3] = f2h2(cosf(x1h[4*u + 2])*ct, cosf(x1h[4*u + 3])*ct);
    }

    // ---- Stages B + C interleaved ----
    const u32* W1W = (const u32*)g_W1H;
    const u32* W2W = (const u32*)g_W2H;
    float cacc[8][4];
    #pragma unroll
    for (int jb = 0; jb < 8; ++jb){ cacc[jb][0]=0.f; cacc[jb][1]=0.f; cacc[jb][2]=0.f; cacc[jb][3]=0.f; }
    #pragma unroll 2
    for (int uu = 0; uu < 16; ++uu){
        float h0[4] = {0.f,0.f,0.f,0.f};
        float h1[4] = {0.f,0.f,0.f,0.f};
        #pragma unroll
        for (int u = 0; u < 4; ++u){
            u32 wb0 = W1W[(u64)(16*uu + g)*32 + 8*u + c];
            u32 wb1 = W1W[(u64)(16*uu + g)*32 + 8*u + c + 4];
            MMA_F16_K16(h0[0],h0[1],h0[2],h0[3], pa[u][0],pa[u][1],pa[u][2],pa[u][3], wb0,wb1);
            wb0 = W1W[(u64)(16*uu + 8 + g)*32 + 8*u + c];
            wb1 = W1W[(u64)(16*uu + 8 + g)*32 + 8*u + c + 4];
            MMA_F16_K16(h1[0],h1[1],h1[2],h1[3], pa[u][0],pa[u][1],pa[u][2],pa[u][3], wb0,wb1);
        }
        float2 b1a = *(const float2*)(b1 + 16*uu + 2*c);
        float2 b1b = *(const float2*)(b1 + 16*uu + 8 + 2*c);
        u32 ca0 = f2h2(fmaxf(h0[0] + b1a.x, 0.f), fmaxf(h0[1] + b1a.y, 0.f));
        u32 ca1 = f2h2(fmaxf(h0[2] + b1a.x, 0.f), fmaxf(h0[3] + b1a.y, 0.f));
        u32 ca2 = f2h2(fmaxf(h1[0] + b1b.x, 0.f), fmaxf(h1[1] + b1b.y, 0.f));
        u32 ca3 = f2h2(fmaxf(h1[2] + b1b.x, 0.f), fmaxf(h1[3] + b1b.y, 0.f));
        #pragma unroll
        for (int jb = 0; jb < 8; ++jb){
            u32 wb0 = W2W[(u64)(8*jb + g)*128 + 8*uu + c];
            u32 wb1 = W2W[(u64)(8*jb + g)*128 + 8*uu + c + 4];
            MMA_F16_K16(cacc[jb][0],cacc[jb][1],cacc[jb][2],cacc[jb][3], ca0,ca1,ca2,ca3, wb0,wb1);
        }
    }

    // ---- Stage C epilogue: + b2 + x1, LN2, store ----
    #pragma unroll
    for (int jb = 0; jb < 8; ++jb){
        float2 b22 = *(const float2*)(b2 + 8*jb + 2*c);
        cacc[jb][0] += b22.x + x1g[2*jb];
        cacc[jb][1] += b22.y + x1g[2*jb+1];
        cacc[jb][2] += b22.x + x1h[2*jb];
        cacc[jb][3] += b22.y + x1h[2*jb+1];
    }
    sg = 0.f; sh = 0.f;
    #pragma unroll
    for (int jb = 0; jb < 8; ++jb){ sg += cacc[jb][0] + cacc[jb][1]; sh += cacc[jb][2] + cacc[jb][3]; }
    sg += __shfl_xor_sync(0xffffffffu, sg, 1);
    sg += __shfl_xor_sync(0xffffffffu, sg, 2);
    sh += __shfl_xor_sync(0xffffffffu, sh, 1);
    sh += __shfl_xor_sync(0xffffffffu, sh, 2);
    mg_ = sg*(1.0f/64.0f); mh_ = sh*(1.0f/64.0f);
    vg_ = 0.f; vh_ = 0.f;
    #pragma unroll
    for (int jb = 0; jb < 8; ++jb){
        cacc[jb][0] -= mg_; cacc[jb][1] -= mg_;
        cacc[jb][2] -= mh_; cacc[jb][3] -= mh_;
        vg_ += cacc[jb][0]*cacc[jb][0] + cacc[jb][1]*cacc[jb][1];
        vh_ += cacc[jb][2]*cacc[jb][2] + cacc[jb][3]*cacc[jb][3];
    }
    vg_ += __shfl_xor_sync(0xffffffffu, vg_, 1);
    vg_ += __shfl_xor_sync(0xffffffffu, vg_, 2);
    vh_ += __shfl_xor_sync(0xffffffffu, vh_, 1);
    vh_ += __shfl_xor_sync(0xffffffffu, vh_, 2);
    rg_ = rsqrtf(vg_*(1.0f/64.0f) + 1e-5f);
    rh_ = rsqrtf(vh_*(1.0f/64.0f) + 1e-5f);
    #pragma unroll
    for (int jb = 0; jb < 8; ++jb){
        float2 g22  = *(const float2*)(g2  + 8*jb + 2*c);
        float2 be22 = *(const float2*)(be2 + 8*jb + 2*c);
        *(float2*)(out + (u64)(r0 + g    )*NE + 8*jb + 2*c) =
            make_float2(cacc[jb][0]*rg_*g22.x + be22.x, cacc[jb][1]*rg_*g22.y + be22.y);
        *(float2*)(out + (u64)(r0 + g + 8)*NE + 8*jb + 2*c) =
            make_float2(cacc[jb][2]*rh_*g22.x + be22.x, cacc[jb][3]*rh_*g22.y + be22.y);
    }
}

extern "C" void kernel_launch(void* const* d_in, const int* in_sizes, int n_in,
                              void* d_out, int out_size)
{
    const float* x   = (const float*)d_in[0];
    const float* Wq  = (const float*)d_in[1];
    const float* bq  = (const float*)d_in[2];
    const float* Wk  = (const float*)d_in[3];
    const float* bk  = (const float*)d_in[4];
    const float* Wv  = (const float*)d_in[5];
    const float* bv  = (const float*)d_in[6];
    const float* Wo  = (const float*)d_in[7];
    const float* bo  = (const float*)d_in[8];
    const float* tha = (const float*)d_in[9];
    const float* thf = (const float*)d_in[10];
    const float* W1  = (const float*)d_in[11];
    const float* b1  = (const float*)d_in[12];
    const float* W2  = (const float*)d_in[13];
    const float* b2  = (const float*)d_in[14];
    const float* g1  = (const float*)d_in[15];
    const float* be1 = (const float*)d_in[16];
    const float* g2  = (const float*)d_in[17];
    const float* be2 = (const float*)d_in[18];
    float* out = (float*)d_out;

    cudaFuncSetAttribute(k_qkv,  cudaFuncAttributeMaxDynamicSharedMemorySize, QKV_SMEM);
    cudaFuncSetAttribute(k_attn, cudaFuncAttributeMaxDynamicSharedMemorySize, ATTN_SMEM);

    k_transpose<<<64, 256>>>(W1, W2, Wq, Wk, Wv, Wo);
    k_qkv<<<NROWS/32, 256, QKV_SMEM>>>(x, bq, bk, bv, tha);
    k_attn<<<dim3(8, 64), 512, ATTN_SMEM>>>();
    k_tail<<<NROWS/64, 128>>>(x, bo, g1, be1, thf, b1, b2, g2, be2, out);
}

// round 10
// speedup vs baseline: 3.5075x; 1.0221x over previous
#include <cuda_runtime.h>
#include <cuda_fp16.h>
#include <math.h>

#define NB 8
#define NT 2048
#define NE 64
#define NH 8
#define NDK 8
#define NFF 256
#define NROWS (NB*NT)

typedef unsigned long long u64;
typedef unsigned u32;

__device__ __forceinline__ u32 f2h2(float lo, float hi){ u32 r; asm("cvt.rn.f16x2.f32 %0,%1,%2;":"=r"(r):"f"(hi),"f"(lo)); return r; }
__device__ __forceinline__ u32 hadd2u(u32 a, u32 b){ u32 r; asm("add.rn.f16x2 %0,%1,%2;":"=r"(r):"r"(a),"r"(b)); return r; }
__device__ __forceinline__ u32 ex2h2(u32 a){ u32 r; asm("ex2.approx.f16x2 %0,%1;":"=r"(r):"r"(a)); return r; }
__device__ __forceinline__ float2 h2f2(u32 a){
    float lo, hi;
    asm("{.reg .b16 l,h; mov.b32 {l,h},%2; cvt.f32.f16 %0,l; cvt.f32.f16 %1,h;}"
        :"=f"(lo),"=f"(hi):"r"(a));
    return make_float2(lo, hi);
}
#define MMA_F16_K8(c0,c1,c2,c3,a0,a1,b0) \
    asm("mma.sync.aligned.m16n8k8.row.col.f32.f16.f16.f32 " \
        "{%0,%1,%2,%3},{%4,%5},{%6},{%0,%1,%2,%3};" \
        : "+f"(c0),"+f"(c1),"+f"(c2),"+f"(c3) : "r"(a0),"r"(a1),"r"(b0))
#define MMA_F16_K16(c0,c1,c2,c3,a0,a1,a2,a3,b0,b1) \
    asm("mma.sync.aligned.m16n8k16.row.col.f32.f16.f16.f32 " \
        "{%0,%1,%2,%3},{%4,%5,%6,%7},{%8,%9},{%0,%1,%2,%3};" \
        : "+f"(c0),"+f"(c1),"+f"(c2),"+f"(c3) \
        : "r"(a0),"r"(a1),"r"(a2),"r"(a3),"r"(b0),"r"(b1))

// Q scale: 1/sqrt(8) * log2(e)
#define QSCALE 0.5100690827241087f

// ---- scratch ----
__device__ __half g_q[NROWS*NE];     // per-head [b*8+h][t][8]
__device__ __half g_k[NROWS*NE];
__device__ __half g_v[NROWS*NE];
__device__ __half g_attn[NROWS*NE];  // row-major [b*T+t][64], f16
__device__ __half g_WqH[NE*NE];      // [j][e] f16 original layout = B-frag [n][k]
__device__ __half g_WkH[NE*NE];
__device__ __half g_WvH[NE*NE];
__device__ __half g_WoH[NE*NE];
__device__ __half g_W1H[NFF*NE];     // [f][e]
__device__ __half g_W2H[NE*NFF];     // [j][f]

__global__ void k_transpose(const float* __restrict__ W1, const float* __restrict__ W2,
                            const float* __restrict__ Wq, const float* __restrict__ Wk,
                            const float* __restrict__ Wv, const float* __restrict__ Wo){
    int i = blockIdx.x*256 + threadIdx.x;
    if (i < NE*NFF){
        g_W1H[i] = __float2half(W1[i]);
        g_W2H[i] = __float2half(W2[i]);
    }
    if (i < NE*NE){
        g_WqH[i] = __float2half(Wq[i]);
        g_WkH[i] = __float2half(Wk[i]);
        g_WvH[i] = __float2half(Wv[i]);
        g_WoH[i] = __float2half(Wo[i]);
    }
}

// ---- K1: tensor-core QKV + cos(.+theta) ----
// Warp = 16 rows, block = 128 thr (64 rows), grid 256.
// Weights f16 in padded smem (stride 36 u32/row: bank = 4g+8u+c, conflict-free).
__global__ __launch_bounds__(128) void k_qkv(
    const float* __restrict__ x,
    const float* __restrict__ bq, const float* __restrict__ bk,
    const float* __restrict__ bv, const float* __restrict__ th)
{
    __shared__ u32 Wsm[3*64*36];     // 27648 B
    int tid = threadIdx.x;
    {
        const u32* srcs[3] = {(const u32*)g_WqH, (const u32*)g_WkH, (const u32*)g_WvH};
        for (int i = tid; i < 3*2048; i += 128){
            int m = i >> 11, rem = i & 2047;
            int j = rem >> 5, k2 = rem & 31;
            Wsm[m*2304 + j*36 + k2] = srcs[m][rem];
        }
    }
    __syncthreads();

    int warp = tid >> 5, lane = tid & 31;
    int g = lane >> 2, c = lane & 3;
    int r0 = blockIdx.x*64 + warp*16;
    int b = r0 >> 11, t0 = r0 & (NT-1);
    const float theta = *th;

    // x A-frags (f16), k-blocks u=0..3
    u32 xa[4][4];
    #pragma unroll
    for (int u = 0; u < 4; ++u){
        float2 v0 = *(const float2*)(x + (u64)(r0 + g    )*NE + 16*u + 2*c);
        float2 v1 = *(const float2*)(x + (u64)(r0 + g + 8)*NE + 16*u + 2*c);
        float2 v2 = *(const float2*)(x + (u64)(r0 + g    )*NE + 16*u + 2*c + 8);
        float2 v3 = *(const float2*)(x + (u64)(r0 + g + 8)*NE + 16*u + 2*c + 8);
        xa[u][0] = f2h2(v0.x, v0.y);
        xa[u][1] = f2h2(v1.x, v1.y);
        xa[u][2] = f2h2(v2.x, v2.y);
        xa[u][3] = f2h2(v3.x, v3.y);
    }

    const float* biases[3] = {bq, bk, bv};
    u32* dsts[3] = {(u32*)g_q, (u32*)g_k, (u32*)g_v};
    #pragma unroll
    for (int p = 0; p < 3; ++p){
        const u32* Wp = Wsm + p*2304;
        const float* bias = biases[p];
        u32* dst = dsts[p];
        float scale = (p == 0) ? QSCALE : 1.0f;
        #pragma unroll
        for (int nb = 0; nb < 8; ++nb){
            float d0=0.f,d1=0.f,d2=0.f,d3=0.f;
            #pragma unroll
            for (int u = 0; u < 4; ++u){
                u32 wb0 = Wp[(8*nb + g)*36 + 8*u + c];
                u32 wb1 = Wp[(8*nb + g)*36 + 8*u + c + 4];
                MMA_F16_K16(d0,d1,d2,d3, xa[u][0],xa[u][1],xa[u][2],xa[u][3], wb0,wb1);
            }
            float2 bb = *(const float2*)(bias + 8*nb + 2*c);
            u32 lo = f2h2(cosf(d0 + bb.x + theta)*scale, cosf(d1 + bb.y + theta)*scale);
            u32 hi = f2h2(cosf(d2 + bb.x + theta)*scale, cosf(d3 + bb.y + theta)*scale);
            dst[((u64)(b*NH + nb)*NT + t0 + g    )*4 + c] = lo;
            dst[((u64)(b*NH + nb)*NT + t0 + g + 8)*4 + c] = hi;
        }
    }
}

// ---- K2: f16 flash attention (unchanged from R8) ----
#define ATTN_SMEM (96*1024)
__global__ void __launch_bounds__(512,2) k_attn()
{
    extern __shared__ u32 smu[];
    u32*   Kh   = smu;
    u32*   Vraw = smu + 8192;
    uint2* Vh   = (uint2*)(smu + 16384);
    int bh = blockIdx.y;
    int tid = threadIdx.x;
    const u32* kg = (const u32*)(g_k + (u64)bh*NT*NDK);
    const u32* vg = (const u32*)(g_v + (u64)bh*NT*NDK);
    for (int i = tid; i < 8192; i += 512){ Kh[i] = kg[i]; Vraw[i] = vg[i]; }
    __syncthreads();
    const unsigned short* vb = (const unsigned short*)Vraw;
    for (int j = tid; j < 4096; j += 512){
        int m = j >> 5, d = (j >> 2) & 7, c = j & 3;
        u32 lo = (u32)vb[(16*m + 2*c    )*8 + d] | ((u32)vb[(16*m + 2*c + 1)*8 + d] << 16);
        u32 hi = (u32)vb[(16*m + 2*c + 8)*8 + d] | ((u32)vb[(16*m + 2*c + 9)*8 + d] << 16);
        Vh[j] = make_uint2(lo, hi);
    }
    __syncthreads();

    int wid = tid >> 5, lane = tid & 31;
    int g = lane >> 2, c = lane & 3;
    int qbase = blockIdx.x*256 + wid*16;
    int b = bh >> 3, h = bh & 7;

    const u32* qg = (const u32*)(g_q + (u64)bh*NT*NDK);
    u32 qa0 = qg[(qbase + g    )*4 + c];
    u32 qa1 = qg[(qbase + g + 8)*4 + c];

    float o0 = 0.f, o1 = 0.f, o2 = 0.f, o3 = 0.f;
    float ls0 = 0.f, ls1 = 0.f;
    const u32*   KpW = Kh + g*4 + c;
    const uint2* VpW = Vh + g*4 + c;

    for (int mg = 0; mg < 32; ++mg){
        u32 hacc0 = 0u, hacc1 = 0u;
        #pragma unroll
        for (int mi = 0; mi < 4; ++mi){
            int m = mg*4 + mi;
            u32 kb0 = KpW[m*64];
            u32 kb1 = KpW[m*64 + 32];
            float s0=0.f,s1=0.f,s2=0.f,s3=0.f;
            MMA_F16_K8(s0,s1,s2,s3, qa0,qa1, kb0);
            float t0=0.f,t1=0.f,t2=0.f,t3=0.f;
            MMA_F16_K8(t0,t1,t2,t3, qa0,qa1, kb1);
            u32 ra0 = ex2h2(f2h2(s0, s1));
            u32 ra1 = ex2h2(f2h2(s2, s3));
            u32 ra2 = ex2h2(f2h2(t0, t1));
            u32 ra3 = ex2h2(f2h2(t2, t3));
            hacc0 = hadd2u(hacc0, hadd2u(ra0, ra2));
            hacc1 = hadd2u(hacc1, hadd2u(ra1, ra3));
            uint2 vv = VpW[m*32];
            MMA_F16_K16(o0,o1,o2,o3, ra0,ra1,ra2,ra3, vv.x, vv.y);
        }
        float2 f0 = h2f2(hacc0); ls0 += f0.x + f0.y;
        float2 f1 = h2f2(hacc1); ls1 += f1.x + f1.y;
    }

    ls0 += __shfl_xor_sync(0xffffffffu, ls0, 1);
    ls0 += __shfl_xor_sync(0xffffffffu, ls0, 2);
    ls1 += __shfl_xor_sync(0xffffffffu, ls1, 1);
    ls1 += __shfl_xor_sync(0xffffffffu, ls1, 2);
    float inv0 = 1.0f/ls0, inv1 = 1.0f/ls1;

    u32* dstw = (u32*)g_attn;
    dstw[((u64)b*NT + qbase + g    )*32 + h*4 + c] = f2h2(o0*inv0, o1*inv0);
    dstw[((u64)b*NT + qbase + g + 8)*32 + h*4 + c] = f2h2(o2*inv1, o3*inv1);
}

// ---- K3: tensor-core fused tail, weights in padded smem ----
// Warp = 16 rows, block = 128 thr, grid 256.
// smem u32 layout: Wo [64][36] @0, W1 [256][36] @2304, W2 [64][132] @11520.
#define TAIL_SMEM (19968*4)
__global__ __launch_bounds__(128) void k_tail(
    const float* __restrict__ x,  const float* __restrict__ bo,
    const float* __restrict__ g1, const float* __restrict__ be1,
    const float* __restrict__ thf,
    const float* __restrict__ b1, const float* __restrict__ b2,
    const float* __restrict__ g2, const float* __restrict__ be2,
    float* __restrict__ out)
{
    extern __shared__ u32 smw[];
    u32* WoS = smw;
    u32* W1S = smw + 2304;
    u32* W2S = smw + 11520;
    int tid = threadIdx.x;
    {
        const u32* WoG = (const u32*)g_WoH;
        const u32* W1G = (const u32*)g_W1H;
        const u32* W2G = (const u32*)g_W2H;
        for (int i = tid; i < 2048; i += 128)
            WoS[(i >> 5)*36 + (i & 31)] = WoG[i];
        for (int i = tid; i < 8192; i += 128)
            W1S[(i >> 5)*36 + (i & 31)] = W1G[i];
        for (int i = tid; i < 8192; i += 128)
            W2S[(i >> 7)*132 + (i & 127)] = W2G[i];
    }
    __syncthreads();

    int warp = tid >> 5, lane = tid & 31;
    int g = lane >> 2, c = lane & 3;
    int r0 = blockIdx.x*64 + warp*16;

    // ---- Stage A: attn @ Wo + bo + x -> LN1 -> x1, cos -> A-frag ----
    const u32* attnW = (const u32*)g_attn;
    u32 qa[4][4];
    #pragma unroll
    for (int u = 0; u < 4; ++u){
        qa[u][0] = attnW[(u64)(r0 + g    )*32 + 8*u + c];
        qa[u][1] = attnW[(u64)(r0 + g + 8)*32 + 8*u + c];
        qa[u][2] = attnW[(u64)(r0 + g    )*32 + 8*u + c + 4];
        qa[u][3] = attnW[(u64)(r0 + g + 8)*32 + 8*u + c + 4];
    }
    float da[8][4];
    #pragma unroll
    for (int nb = 0; nb < 8; ++nb){
        float d0=0.f,d1=0.f,d2=0.f,d3=0.f;
        #pragma unroll
        for (int u = 0; u < 4; ++u){
            u32 wb0 = WoS[(8*nb + g)*36 + 8*u + c];
            u32 wb1 = WoS[(8*nb + g)*36 + 8*u + c + 4];
            MMA_F16_K16(d0,d1,d2,d3, qa[u][0],qa[u][1],qa[u][2],qa[u][3], wb0,wb1);
        }
        float2 bo2 = *(const float2*)(bo + 8*nb + 2*c);
        float2 xg = *(const float2*)(x + (u64)(r0 + g    )*NE + 8*nb + 2*c);
        float2 xh = *(const float2*)(x + (u64)(r0 + g + 8)*NE + 8*nb + 2*c);
        da[nb][0] = d0 + bo2.x + xg.x;
        da[nb][1] = d1 + bo2.y + xg.y;
        da[nb][2] = d2 + bo2.x + xh.x;
        da[nb][3] = d3 + bo2.y + xh.y;
    }
    float sg = 0.f, sh = 0.f;
    #pragma unroll
    for (int nb = 0; nb < 8; ++nb){ sg += da[nb][0] + da[nb][1]; sh += da[nb][2] + da[nb][3]; }
    sg += __shfl_xor_sync(0xffffffffu, sg, 1);
    sg += __shfl_xor_sync(0xffffffffu, sg, 2);
    sh += __shfl_xor_sync(0xffffffffu, sh, 1);
    sh += __shfl_xor_sync(0xffffffffu, sh, 2);
    float mg_ = sg*(1.0f/64.0f), mh_ = sh*(1.0f/64.0f);
    float vg_ = 0.f, vh_ = 0.f;
    #pragma unroll
    for (int nb = 0; nb < 8; ++nb){
        da[nb][0] -= mg_; da[nb][1] -= mg_;
        da[nb][2] -= mh_; da[nb][3] -= mh_;
        vg_ += da[nb][0]*da[nb][0] + da[nb][1]*da[nb][1];
        vh_ += da[nb][2]*da[nb][2] + da[nb][3]*da[nb][3];
    }
    vg_ += __shfl_xor_sync(0xffffffffu, vg_, 1);
    vg_ += __shfl_xor_sync(0xffffffffu, vg_, 2);
    vh_ += __shfl_xor_sync(0xffffffffu, vh_, 1);
    vh_ += __shfl_xor_sync(0xffffffffu, vh_, 2);
    float rg_ = rsqrtf(vg_*(1.0f/64.0f) + 1e-5f);
    float rh_ = rsqrtf(vh_*(1.0f/64.0f) + 1e-5f);
    float ct = cosf(*thf);
    float x1g[16], x1h[16];
    u32 pa[4][4];
    #pragma unroll
    for (int nb = 0; nb < 8; ++nb){
        float2 g12  = *(const float2*)(g1  + 8*nb + 2*c);
        float2 be12 = *(const float2*)(be1 + 8*nb + 2*c);
        x1g[2*nb]   = da[nb][0]*rg_*g12.x + be12.x;
        x1g[2*nb+1] = da[nb][1]*rg_*g12.y + be12.y;
        x1h[2*nb]   = da[nb][2]*rh_*g12.x + be12.x;
        x1h[2*nb+1] = da[nb][3]*rh_*g12.y + be12.y;
    }
    #pragma unroll
    for (int u = 0; u < 4; ++u){
        pa[u][0] = f2h2(cosf(x1g[4*u    ])*ct, cosf(x1g[4*u + 1])*ct);
        pa[u][1] = f2h2(cosf(x1h[4*u    ])*ct, cosf(x1h[4*u + 1])*ct);
        pa[u][2] = f2h2(cosf(x1g[4*u + 2])*ct, cosf(x1g[4*u + 3])*ct);
        pa[u][3] = f2h2(cosf(x1h[4*u + 2])*ct, cosf(x1h[4*u + 3])*ct);
    }

    // ---- Stages B + C interleaved ----
    float cacc[8][4];
    #pragma unroll
    for (int jb = 0; jb < 8; ++jb){ cacc[jb][0]=0.f; cacc[jb][1]=0.f; cacc[jb][2]=0.f; cacc[jb][3]=0.f; }
    #pragma unroll 2
    for (int uu = 0; uu < 16; ++uu){
        float h0[4] = {0.f,0.f,0.f,0.f};
        float h1[4] = {0.f,0.f,0.f,0.f};
        #pragma unroll
        for (int u = 0; u < 4; ++u){
            u32 wb0 = W1S[(16*uu + g)*36 + 8*u + c];
            u32 wb1 = W1S[(16*uu + g)*36 + 8*u + c + 4];
            MMA_F16_K16(h0[0],h0[1],h0[2],h0[3], pa[u][0],pa[u][1],pa[u][2],pa[u][3], wb0,wb1);
            wb0 = W1S[(16*uu + 8 + g)*36 + 8*u + c];
            wb1 = W1S[(16*uu + 8 + g)*36 + 8*u + c + 4];
            MMA_F16_K16(h1[0],h1[1],h1[2],h1[3], pa[u][0],pa[u][1],pa[u][2],pa[u][3], wb0,wb1);
        }
        float2 b1a = *(const float2*)(b1 + 16*uu + 2*c);
        float2 b1b = *(const float2*)(b1 + 16*uu + 8 + 2*c);
        u32 ca0 = f2h2(fmaxf(h0[0] + b1a.x, 0.f), fmaxf(h0[1] + b1a.y, 0.f));
        u32 ca1 = f2h2(fmaxf(h0[2] + b1a.x, 0.f), fmaxf(h0[3] + b1a.y, 0.f));
        u32 ca2 = f2h2(fmaxf(h1[0] + b1b.x, 0.f), fmaxf(h1[1] + b1b.y, 0.f));
        u32 ca3 = f2h2(fmaxf(h1[2] + b1b.x, 0.f), fmaxf(h1[3] + b1b.y, 0.f));
        #pragma unroll
        for (int jb = 0; jb < 8; ++jb){
            u32 wb0 = W2S[(8*jb + g)*132 + 8*uu + c];
            u32 wb1 = W2S[(8*jb + g)*132 + 8*uu + c + 4];
            MMA_F16_K16(cacc[jb][0],cacc[jb][1],cacc[jb][2],cacc[jb][3], ca0,ca1,ca2,ca3, wb0,wb1);
        }
    }

    // ---- Stage C epilogue: + b2 + x1, LN2, store ----
    #pragma unroll
    for (int jb = 0; jb < 8; ++jb){
        float2 b22 = *(const float2*)(b2 + 8*jb + 2*c);
        cacc[jb][0] += b22.x + x1g[2*jb];
        cacc[jb][1] += b22.y + x1g[2*jb+1];
        cacc[jb][2] += b22.x + x1h[2*jb];
        cacc[jb][3] += b22.y + x1h[2*jb+1];
    }
    sg = 0.f; sh = 0.f;
    #pragma unroll
    for (int jb = 0; jb < 8; ++jb){ sg += cacc[jb][0] + cacc[jb][1]; sh += cacc[jb][2] + cacc[jb][3]; }
    sg += __shfl_xor_sync(0xffffffffu, sg, 1);
    sg += __shfl_xor_sync(0xffffffffu, sg, 2);
    sh += __shfl_xor_sync(0xffffffffu, sh, 1);
    sh += __shfl_xor_sync(0xffffffffu, sh, 2);
    mg_ = sg*(1.0f/64.0f); mh_ = sh*(1.0f/64.0f);
    vg_ = 0.f; vh_ = 0.f;
    #pragma unroll
    for (int jb = 0; jb < 8; ++jb){
        cacc[jb][0] -= mg_; cacc[jb][1] -= mg_;
        cacc[jb][2] -= mh_; cacc[jb][3] -= mh_;
        vg_ += cacc[jb][0]*cacc[jb][0] + cacc[jb][1]*cacc[jb][1];
        vh_ += cacc[jb][2]*cacc[jb][2] + cacc[jb][3]*cacc[jb][3];
    }
    vg_ += __shfl_xor_sync(0xffffffffu, vg_, 1);
    vg_ += __shfl_xor_sync(0xffffffffu, vg_, 2);
    vh_ += __shfl_xor_sync(0xffffffffu, vh_, 1);
    vh_ += __shfl_xor_sync(0xffffffffu, vh_, 2);
    rg_ = rsqrtf(vg_*(1.0f/64.0f) + 1e-5f);
    rh_ = rsqrtf(vh_*(1.0f/64.0f) + 1e-5f);
    #pragma unroll
    for (int jb = 0; jb < 8; ++jb){
        float2 g22  = *(const float2*)(g2  + 8*jb + 2*c);
        float2 be22 = *(const float2*)(be2 + 8*jb + 2*c);
        *(float2*)(out + (u64)(r0 + g    )*NE + 8*jb + 2*c) =
            make_float2(cacc[jb][0]*rg_*g22.x + be22.x, cacc[jb][1]*rg_*g22.y + be22.y);
        *(float2*)(out + (u64)(r0 + g + 8)*NE + 8*jb + 2*c) =
            make_float2(cacc[jb][2]*rh_*g22.x + be22.x, cacc[jb][3]*rh_*g22.y + be22.y);
    }
}

extern "C" void kernel_launch(void* const* d_in, const int* in_sizes, int n_in,
                              void* d_out, int out_size)
{
    const float* x   = (const float*)d_in[0];
    const float* Wq  = (const float*)d_in[1];
    const float* bq  = (const float*)d_in[2];
    const float* Wk  = (const float*)d_in[3];
    const float* bk  = (const float*)d_in[4];
    const float* Wv  = (const float*)d_in[5];
    const float* bv  = (const float*)d_in[6];
    const float* Wo  = (const float*)d_in[7];
    const float* bo  = (const float*)d_in[8];
    const float* tha = (const float*)d_in[9];
    const float* thf = (const float*)d_in[10];
    const float* W1  = (const float*)d_in[11];
    const float* b1  = (const float*)d_in[12];
    const float* W2  = (const float*)d_in[13];
    const float* b2  = (const float*)d_in[14];
    const float* g1  = (const float*)d_in[15];
    const float* be1 = (const float*)d_in[16];
    const float* g2  = (const float*)d_in[17];
    const float* be2 = (const float*)d_in[18];
    float* out = (float*)d_out;

    cudaFuncSetAttribute(k_attn, cudaFuncAttributeMaxDynamicSharedMemorySize, ATTN_SMEM);
    cudaFuncSetAttribute(k_tail, cudaFuncAttributeMaxDynamicSharedMemorySize, TAIL_SMEM);

    k_transpose<<<64, 256>>>(W1, W2, Wq, Wk, Wv, Wo);
    k_qkv<<<NROWS/64, 128>>>(x, bq, bk, bv, tha);
    k_attn<<<dim3(8, 64), 512, ATTN_SMEM>>>();
    k_tail<<<NROWS/64, 128, TAIL_SMEM>>>(x, bo, g1, be1, thf, b1, b2, g2, be2, out);
}

// round 11
// speedup vs baseline: 3.7314x; 1.0638x over previous
#include <cuda_runtime.h>
#include <cuda_fp16.h>
#include <math.h>

#define NB 8
#define NT 2048
#define NE 64
#define NH 8
#define NDK 8
#define NFF 256
#define NROWS (NB*NT)

typedef unsigned long long u64;
typedef unsigned u32;

__device__ __forceinline__ u32 f2h2(float lo, float hi){ u32 r; asm("cvt.rn.f16x2.f32 %0,%1,%2;":"=r"(r):"f"(hi),"f"(lo)); return r; }
__device__ __forceinline__ u32 hadd2u(u32 a, u32 b){ u32 r; asm("add.rn.f16x2 %0,%1,%2;":"=r"(r):"r"(a),"r"(b)); return r; }
__device__ __forceinline__ u32 ex2h2(u32 a){ u32 r; asm("ex2.approx.f16x2 %0,%1;":"=r"(r):"r"(a)); return r; }
__device__ __forceinline__ float2 h2f2(u32 a){
    float lo, hi;
    asm("{.reg .b16 l,h; mov.b32 {l,h},%2; cvt.f32.f16 %0,l; cvt.f32.f16 %1,h;}"
        :"=f"(lo),"=f"(hi):"r"(a));
    return make_float2(lo, hi);
}
#define MMA_F16_K8(c0,c1,c2,c3,a0,a1,b0) \
    asm("mma.sync.aligned.m16n8k8.row.col.f32.f16.f16.f32 " \
        "{%0,%1,%2,%3},{%4,%5},{%6},{%0,%1,%2,%3};" \
        : "+f"(c0),"+f"(c1),"+f"(c2),"+f"(c3) : "r"(a0),"r"(a1),"r"(b0))
#define MMA_F16_K16(c0,c1,c2,c3,a0,a1,a2,a3,b0,b1) \
    asm("mma.sync.aligned.m16n8k16.row.col.f32.f16.f16.f32 " \
        "{%0,%1,%2,%3},{%4,%5,%6,%7},{%8,%9},{%0,%1,%2,%3};" \
        : "+f"(c0),"+f"(c1),"+f"(c2),"+f"(c3) \
        : "r"(a0),"r"(a1),"r"(a2),"r"(a3),"r"(b0),"r"(b1))

// Q scale: 1/sqrt(8) * log2(e)
#define QSCALE 0.5100690827241087f

// ---- scratch ----
__device__ __half g_q[NROWS*NE];     // per-head [b*8+h][t][8]
__device__ __half g_k[NROWS*NE];
__device__ __half g_v[NROWS*NE];
__device__ __half g_attn[NROWS*NE];  // row-major [b*T+t][64], f16
// Paired B-frag weight layouts: idx = n*(K/16)*4 + u*4 + c -> uint2 (b0, b1)
__device__ uint2 g_WqP[1024];
__device__ uint2 g_WkP[1024];
__device__ uint2 g_WvP[1024];
__device__ uint2 g_WoP[1024];
__device__ uint2 g_W1P[4096];        // n=256 rows, K=64
__device__ uint2 g_W2P[4096];        // n=64 rows, K=256

__global__ void k_transpose(const float* __restrict__ W1, const float* __restrict__ W2,
                            const float* __restrict__ Wq, const float* __restrict__ Wk,
                            const float* __restrict__ Wv, const float* __restrict__ Wo){
    int i = blockIdx.x*256 + threadIdx.x;     // grid 16 -> 4096 threads
    if (i < 1024){
        int n = i >> 4, u = (i >> 2) & 3, c = i & 3;
        int base = n*64 + u*16 + 2*c;
        g_WqP[i] = make_uint2(f2h2(Wq[base],Wq[base+1]), f2h2(Wq[base+8],Wq[base+9]));
        g_WkP[i] = make_uint2(f2h2(Wk[base],Wk[base+1]), f2h2(Wk[base+8],Wk[base+9]));
        g_WvP[i] = make_uint2(f2h2(Wv[base],Wv[base+1]), f2h2(Wv[base+8],Wv[base+9]));
        g_WoP[i] = make_uint2(f2h2(Wo[base],Wo[base+1]), f2h2(Wo[base+8],Wo[base+9]));
    }
    if (i < 4096){
        int f = i >> 4, u = (i >> 2) & 3, c = i & 3;
        int base = f*64 + u*16 + 2*c;
        g_W1P[i] = make_uint2(f2h2(W1[base],W1[base+1]), f2h2(W1[base+8],W1[base+9]));
        int j = i >> 6, uu = (i >> 2) & 15, c2 = i & 3;
        int b2i = j*256 + uu*16 + 2*c2;
        g_W2P[i] = make_uint2(f2h2(W2[b2i],W2[b2i+1]), f2h2(W2[b2i+8],W2[b2i+9]));
    }
}

// ---- K1: tensor-core QKV + cos(.+theta). Zero smem, paired LDG.64 weights.
// Warp = 16 rows, block = 64 thr (32 rows), grid 512.
__global__ __launch_bounds__(64) void k_qkv(
    const float* __restrict__ x,
    const float* __restrict__ bq, const float* __restrict__ bk,
    const float* __restrict__ bv, const float* __restrict__ th)
{
    int warp = threadIdx.x >> 5, lane = threadIdx.x & 31;
    int g = lane >> 2, c = lane & 3;
    int r0 = blockIdx.x*32 + warp*16;
    int b = r0 >> 11, t0 = r0 & (NT-1);
    const float theta = *th;

    u32 xa[4][4];
    #pragma unroll
    for (int u = 0; u < 4; ++u){
        float2 v0 = *(const float2*)(x + (u64)(r0 + g    )*NE + 16*u + 2*c);
        float2 v1 = *(const float2*)(x + (u64)(r0 + g + 8)*NE + 16*u + 2*c);
        float2 v2 = *(const float2*)(x + (u64)(r0 + g    )*NE + 16*u + 2*c + 8);
        float2 v3 = *(const float2*)(x + (u64)(r0 + g + 8)*NE + 16*u + 2*c + 8);
        xa[u][0] = f2h2(v0.x, v0.y);
        xa[u][1] = f2h2(v1.x, v1.y);
        xa[u][2] = f2h2(v2.x, v2.y);
        xa[u][3] = f2h2(v3.x, v3.y);
    }

    const uint2* WPs[3] = {g_WqP, g_WkP, g_WvP};
    const float* biases[3] = {bq, bk, bv};
    u32* dsts[3] = {(u32*)g_q, (u32*)g_k, (u32*)g_v};
    #pragma unroll
    for (int p = 0; p < 3; ++p){
        const uint2* WP = WPs[p];
        const float* bias = biases[p];
        u32* dst = dsts[p];
        float scale = (p == 0) ? QSCALE : 1.0f;
        #pragma unroll
        for (int nb = 0; nb < 8; ++nb){
            float dA0=0.f,dA1=0.f,dA2=0.f,dA3=0.f;
            float dB0=0.f,dB1=0.f,dB2=0.f,dB3=0.f;
            #pragma unroll
            for (int u = 0; u < 4; u += 2){
                uint2 w0 = WP[(8*nb + g)*16 + u*4 + c];
                uint2 w1 = WP[(8*nb + g)*16 + (u+1)*4 + c];
                MMA_F16_K16(dA0,dA1,dA2,dA3, xa[u  ][0],xa[u  ][1],xa[u  ][2],xa[u  ][3], w0.x,w0.y);
                MMA_F16_K16(dB0,dB1,dB2,dB3, xa[u+1][0],xa[u+1][1],xa[u+1][2],xa[u+1][3], w1.x,w1.y);
            }
            float d0 = dA0+dB0, d1 = dA1+dB1, d2 = dA2+dB2, d3 = dA3+dB3;
            float2 bb = *(const float2*)(bias + 8*nb + 2*c);
            u32 lo = f2h2(cosf(d0 + bb.x + theta)*scale, cosf(d1 + bb.y + theta)*scale);
            u32 hi = f2h2(cosf(d2 + bb.x + theta)*scale, cosf(d3 + bb.y + theta)*scale);
            dst[((u64)(b*NH + nb)*NT + t0 + g    )*4 + c] = lo;
            dst[((u64)(b*NH + nb)*NT + t0 + g + 8)*4 + c] = hi;
        }
    }
}

// ---- K2: f16 flash attention (unchanged) ----
#define ATTN_SMEM (96*1024)
__global__ void __launch_bounds__(512,2) k_attn()
{
    extern __shared__ u32 smu[];
    u32*   Kh   = smu;
    u32*   Vraw = smu + 8192;
    uint2* Vh   = (uint2*)(smu + 16384);
    int bh = blockIdx.y;
    int tid = threadIdx.x;
    const u32* kg = (const u32*)(g_k + (u64)bh*NT*NDK);
    const u32* vg = (const u32*)(g_v + (u64)bh*NT*NDK);
    for (int i = tid; i < 8192; i += 512){ Kh[i] = kg[i]; Vraw[i] = vg[i]; }
    __syncthreads();
    const unsigned short* vb = (const unsigned short*)Vraw;
    for (int j = tid; j < 4096; j += 512){
        int m = j >> 5, d = (j >> 2) & 7, c = j & 3;
        u32 lo = (u32)vb[(16*m + 2*c    )*8 + d] | ((u32)vb[(16*m + 2*c + 1)*8 + d] << 16);
        u32 hi = (u32)vb[(16*m + 2*c + 8)*8 + d] | ((u32)vb[(16*m + 2*c + 9)*8 + d] << 16);
        Vh[j] = make_uint2(lo, hi);
    }
    __syncthreads();

    int wid = tid >> 5, lane = tid & 31;
    int g = lane >> 2, c = lane & 3;
    int qbase = blockIdx.x*256 + wid*16;
    int b = bh >> 3, h = bh & 7;

    const u32* qg = (const u32*)(g_q + (u64)bh*NT*NDK);
    u32 qa0 = qg[(qbase + g    )*4 + c];
    u32 qa1 = qg[(qbase + g + 8)*4 + c];

    float o0 = 0.f, o1 = 0.f, o2 = 0.f, o3 = 0.f;
    float ls0 = 0.f, ls1 = 0.f;
    const u32*   KpW = Kh + g*4 + c;
    const uint2* VpW = Vh + g*4 + c;

    for (int mg = 0; mg < 32; ++mg){
        u32 hacc0 = 0u, hacc1 = 0u;
        #pragma unroll
        for (int mi = 0; mi < 4; ++mi){
            int m = mg*4 + mi;
            u32 kb0 = KpW[m*64];
            u32 kb1 = KpW[m*64 + 32];
            float s0=0.f,s1=0.f,s2=0.f,s3=0.f;
            MMA_F16_K8(s0,s1,s2,s3, qa0,qa1, kb0);
            float t0=0.f,t1=0.f,t2=0.f,t3=0.f;
            MMA_F16_K8(t0,t1,t2,t3, qa0,qa1, kb1);
            u32 ra0 = ex2h2(f2h2(s0, s1));
            u32 ra1 = ex2h2(f2h2(s2, s3));
            u32 ra2 = ex2h2(f2h2(t0, t1));
            u32 ra3 = ex2h2(f2h2(t2, t3));
            hacc0 = hadd2u(hacc0, hadd2u(ra0, ra2));
            hacc1 = hadd2u(hacc1, hadd2u(ra1, ra3));
            uint2 vv = VpW[m*32];
            MMA_F16_K16(o0,o1,o2,o3, ra0,ra1,ra2,ra3, vv.x, vv.y);
        }
        float2 f0 = h2f2(hacc0); ls0 += f0.x + f0.y;
        float2 f1 = h2f2(hacc1); ls1 += f1.x + f1.y;
    }

    ls0 += __shfl_xor_sync(0xffffffffu, ls0, 1);
    ls0 += __shfl_xor_sync(0xffffffffu, ls0, 2);
    ls1 += __shfl_xor_sync(0xffffffffu, ls1, 1);
    ls1 += __shfl_xor_sync(0xffffffffu, ls1, 2);
    float inv0 = 1.0f/ls0, inv1 = 1.0f/ls1;

    u32* dstw = (u32*)g_attn;
    dstw[((u64)b*NT + qbase + g    )*32 + h*4 + c] = f2h2(o0*inv0, o1*inv0);
    dstw[((u64)b*NT + qbase + g + 8)*32 + h*4 + c] = f2h2(o2*inv1, o3*inv1);
}

// ---- K3: tensor-core fused tail, zero smem, paired LDG.64 weights ----
// Warp = 16 rows, block = 64 thr (32 rows), grid 512.
__global__ __launch_bounds__(64) void k_tail(
    const float* __restrict__ x,  const float* __restrict__ bo,
    const float* __restrict__ g1, const float* __restrict__ be1,
    const float* __restrict__ thf,
    const float* __restrict__ b1, const float* __restrict__ b2,
    const float* __restrict__ g2, const float* __restrict__ be2,
    float* __restrict__ out)
{
    int warp = threadIdx.x >> 5, lane = threadIdx.x & 31;
    int g = lane >> 2, c = lane & 3;
    int r0 = blockIdx.x*32 + warp*16;

    // ---- Stage A: attn @ Wo + bo + x -> LN1 -> x1, cos -> A-frag ----
    const u32* attnW = (const u32*)g_attn;
    u32 qa[4][4];
    #pragma unroll
    for (int u = 0; u < 4; ++u){
        qa[u][0] = attnW[(u64)(r0 + g    )*32 + 8*u + c];
        qa[u][1] = attnW[(u64)(r0 + g + 8)*32 + 8*u + c];
        qa[u][2] = attnW[(u64)(r0 + g    )*32 + 8*u + c + 4];
        qa[u][3] = attnW[(u64)(r0 + g + 8)*32 + 8*u + c + 4];
    }
    float da[8][4];
    #pragma unroll
    for (int nb = 0; nb < 8; ++nb){
        float dA0=0.f,dA1=0.f,dA2=0.f,dA3=0.f;
        float dB0=0.f,dB1=0.f,dB2=0.f,dB3=0.f;
        #pragma unroll
        for (int u = 0; u < 4; u += 2){
            uint2 w0 = g_WoP[(8*nb + g)*16 + u*4 + c];
            uint2 w1 = g_WoP[(8*nb + g)*16 + (u+1)*4 + c];
            MMA_F16_K16(dA0,dA1,dA2,dA3, qa[u  ][0],qa[u  ][1],qa[u  ][2],qa[u  ][3], w0.x,w0.y);
            MMA_F16_K16(dB0,dB1,dB2,dB3, qa[u+1][0],qa[u+1][1],qa[u+1][2],qa[u+1][3], w1.x,w1.y);
        }
        float2 bo2 = *(const float2*)(bo + 8*nb + 2*c);
        float2 xg = *(const float2*)(x + (u64)(r0 + g    )*NE + 8*nb + 2*c);
        float2 xh = *(const float2*)(x + (u64)(r0 + g + 8)*NE + 8*nb + 2*c);
        da[nb][0] = dA0 + dB0 + bo2.x + xg.x;
        da[nb][1] = dA1 + dB1 + bo2.y + xg.y;
        da[nb][2] = dA2 + dB2 + bo2.x + xh.x;
        da[nb][3] = dA3 + dB3 + bo2.y + xh.y;
    }
    float sg = 0.f, sh = 0.f;
    #pragma unroll
    for (int nb = 0; nb < 8; ++nb){ sg += da[nb][0] + da[nb][1]; sh += da[nb][2] + da[nb][3]; }
    sg += __shfl_xor_sync(0xffffffffu, sg, 1);
    sg += __shfl_xor_sync(0xffffffffu, sg, 2);
    sh += __shfl_xor_sync(0xffffffffu, sh, 1);
    sh += __shfl_xor_sync(0xffffffffu, sh, 2);
    float mg_ = sg*(1.0f/64.0f), mh_ = sh*(1.0f/64.0f);
    float vg_ = 0.f, vh_ = 0.f;
    #pragma unroll
    for (int nb = 0; nb < 8; ++nb){
        da[nb][0] -= mg_; da[nb][1] -= mg_;
        da[nb][2] -= mh_; da[nb][3] -= mh_;
        vg_ += da[nb][0]*da[nb][0] + da[nb][1]*da[nb][1];
        vh_ += da[nb][2]*da[nb][2] + da[nb][3]*da[nb][3];
    }
    vg_ += __shfl_xor_sync(0xffffffffu, vg_, 1);
    vg_ += __shfl_xor_sync(0xffffffffu, vg_, 2);
    vh_ += __shfl_xor_sync(0xffffffffu, vh_, 1);
    vh_ += __shfl_xor_sync(0xffffffffu, vh_, 2);
    float rg_ = rsqrtf(vg_*(1.0f/64.0f) + 1e-5f);
    float rh_ = rsqrtf(vh_*(1.0f/64.0f) + 1e-5f);
    float ct = cosf(*thf);
    float x1g[16], x1h[16];
    u32 pa[4][4];
    #pragma unroll
    for (int nb = 0; nb < 8; ++nb){
        float2 g12  = *(const float2*)(g1  + 8*nb + 2*c);
        float2 be12 = *(const float2*)(be1 + 8*nb + 2*c);
        x1g[2*nb]   = da[nb][0]*rg_*g12.x + be12.x;
        x1g[2*nb+1] = da[nb][1]*rg_*g12.y + be12.y;
        x1h[2*nb]   = da[nb][2]*rh_*g12.x + be12.x;
        x1h[2*nb+1] = da[nb][3]*rh_*g12.y + be12.y;
    }
    #pragma unroll
    for (int u = 0; u < 4; ++u){
        pa[u][0] = f2h2(cosf(x1g[4*u    ])*ct, cosf(x1g[4*u + 1])*ct);
        pa[u][1] = f2h2(cosf(x1h[4*u    ])*ct, cosf(x1h[4*u + 1])*ct);
        pa[u][2] = f2h2(cosf(x1g[4*u + 2])*ct, cosf(x1g[4*u + 3])*ct);
        pa[u][3] = f2h2(cosf(x1h[4*u + 2])*ct, cosf(x1h[4*u + 3])*ct);
    }

    // ---- Stages B + C interleaved ----
    float cacc[8][4];
    #pragma unroll
    for (int jb = 0; jb < 8; ++jb){ cacc[jb][0]=0.f; cacc[jb][1]=0.f; cacc[jb][2]=0.f; cacc[jb][3]=0.f; }
    #pragma unroll 2
    for (int uu = 0; uu < 16; ++uu){
        float h0a[4] = {0.f,0.f,0.f,0.f};
        float h0b[4] = {0.f,0.f,0.f,0.f};
        float h1a[4] = {0.f,0.f,0.f,0.f};
        float h1b[4] = {0.f,0.f,0.f,0.f};
        #pragma unroll
        for (int u = 0; u < 4; u += 2){
            uint2 w0 = g_W1P[(16*uu + g)*16 + u*4 + c];
            uint2 w1 = g_W1P[(16*uu + g)*16 + (u+1)*4 + c];
            uint2 w2 = g_W1P[(16*uu + 8 + g)*16 + u*4 + c];
            uint2 w3 = g_W1P[(16*uu + 8 + g)*16 + (u+1)*4 + c];
            MMA_F16_K16(h0a[0],h0a[1],h0a[2],h0a[3], pa[u  ][0],pa[u  ][1],pa[u  ][2],pa[u  ][3], w0.x,w0.y);
            MMA_F16_K16(h0b[0],h0b[1],h0b[2],h0b[3], pa[u+1][0],pa[u+1][1],pa[u+1][2],pa[u+1][3], w1.x,w1.y);
            MMA_F16_K16(h1a[0],h1a[1],h1a[2],h1a[3], pa[u  ][0],pa[u  ][1],pa[u  ][2],pa[u  ][3], w2.x,w2.y);
            MMA_F16_K16(h1b[0],h1b[1],h1b[2],h1b[3], pa[u+1][0],pa[u+1][1],pa[u+1][2],pa[u+1][3], w3.x,w3.y);
        }
        float2 b1a = *(const float2*)(b1 + 16*uu + 2*c);
        float2 b1b = *(const float2*)(b1 + 16*uu + 8 + 2*c);
        u32 ca0 = f2h2(fmaxf(h0a[0]+h0b[0] + b1a.x, 0.f), fmaxf(h0a[1]+h0b[1] + b1a.y, 0.f));
        u32 ca1 = f2h2(fmaxf(h0a[2]+h0b[2] + b1a.x, 0.f), fmaxf(h0a[3]+h0b[3] + b1a.y, 0.f));
        u32 ca2 = f2h2(fmaxf(h1a[0]+h1b[0] + b1b.x, 0.f), fmaxf(h1a[1]+h1b[1] + b1b.y, 0.f));
        u32 ca3 = f2h2(fmaxf(h1a[2]+h1b[2] + b1b.x, 0.f), fmaxf(h1a[3]+h1b[3] + b1b.y, 0.f));
        #pragma unroll
        for (int jb = 0; jb < 8; ++jb){
            uint2 w2p = g_W2P[(8*jb + g)*64 + uu*4 + c];
            MMA_F16_K16(cacc[jb][0],cacc[jb][1],cacc[jb][2],cacc[jb][3], ca0,ca1,ca2,ca3, w2p.x,w2p.y);
        }
    }

    // ---- Stage C epilogue: + b2 + x1, LN2, store ----
    #pragma unroll
    for (int jb = 0; jb < 8; ++jb){
        float2 b22 = *(const float2*)(b2 + 8*jb + 2*c);
        cacc[jb][0] += b22.x + x1g[2*jb];
        cacc[jb][1] += b22.y + x1g[2*jb+1];
        cacc[jb][2] += b22.x + x1h[2*jb];
        cacc[jb][3] += b22.y + x1h[2*jb+1];
    }
    sg = 0.f; sh = 0.f;
    #pragma unroll
    for (int jb = 0; jb < 8; ++jb){ sg += cacc[jb][0] + cacc[jb][1]; sh += cacc[jb][2] + cacc[jb][3]; }
    sg += __shfl_xor_sync(0xffffffffu, sg, 1);
    sg += __shfl_xor_sync(0xffffffffu, sg, 2);
    sh += __shfl_xor_sync(0xffffffffu, sh, 1);
    sh += __shfl_xor_sync(0xffffffffu, sh, 2);
    mg_ = sg*(1.0f/64.0f); mh_ = sh*(1.0f/64.0f);
    vg_ = 0.f; vh_ = 0.f;
    #pragma unroll
    for (int jb = 0; jb < 8; ++jb){
        cacc[jb][0] -= mg_; cacc[jb][1] -= mg_;
        cacc[jb][2] -= mh_; cacc[jb][3] -= mh_;
        vg_ += cacc[jb][0]*cacc[jb][0] + cacc[jb][1]*cacc[jb][1];
        vh_ += cacc[jb][2]*cacc[jb][2] + cacc[jb][3]*cacc[jb][3];
    }
    vg_ += __shfl_xor_sync(0xffffffffu, vg_, 1);
    vg_ += __shfl_xor_sync(0xffffffffu, vg_, 2);
    vh_ += __shfl_xor_sync(0xffffffffu, vh_, 1);
    vh_ += __shfl_xor_sync(0xffffffffu, vh_, 2);
    rg_ = rsqrtf(vg_*(1.0f/64.0f) + 1e-5f);
    rh_ = rsqrtf(vh_*(1.0f/64.0f) + 1e-5f);
    #pragma unroll
    for (int jb = 0; jb < 8; ++jb){
        float2 g22  = *(const float2*)(g2  + 8*jb + 2*c);
        float2 be22 = *(const float2*)(be2 + 8*jb + 2*c);
        *(float2*)(out + (u64)(r0 + g    )*NE + 8*jb + 2*c) =
            make_float2(cacc[jb][0]*rg_*g22.x + be22.x, cacc[jb][1]*rg_*g22.y + be22.y);
        *(float2*)(out + (u64)(r0 + g + 8)*NE + 8*jb + 2*c) =
            make_float2(cacc[jb][2]*rh_*g22.x + be22.x, cacc[jb][3]*rh_*g22.y + be22.y);
    }
}

extern "C" void kernel_launch(void* const* d_in, const int* in_sizes, int n_in,
                              void* d_out, int out_size)
{
    const float* x   = (const float*)d_in[0];
    const float* Wq  = (const float*)d_in[1];
    const float* bq  = (const float*)d_in[2];
    const float* Wk  = (const float*)d_in[3];
    const float* bk  = (const float*)d_in[4];
    const float* Wv  = (const float*)d_in[5];
    const float* bv  = (const float*)d_in[6];
    const float* Wo  = (const float*)d_in[7];
    const float* bo  = (const float*)d_in[8];
    const float* tha = (const float*)d_in[9];
    const float* thf = (const float*)d_in[10];
    const float* W1  = (const float*)d_in[11];
    const float* b1  = (const float*)d_in[12];
    const float* W2  = (const float*)d_in[13];
    const float* b2  = (const float*)d_in[14];
    const float* g1  = (const float*)d_in[15];
    const float* be1 = (const float*)d_in[16];
    const float* g2  = (const float*)d_in[17];
    const float* be2 = (const float*)d_in[18];
    float* out = (float*)d_out;

    cudaFuncSetAttribute(k_attn, cudaFuncAttributeMaxDynamicSharedMemorySize, ATTN_SMEM);

    k_transpose<<<16, 256>>>(W1, W2, Wq, Wk, Wv, Wo);
    k_qkv<<<NROWS/32, 64>>>(x, bq, bk, bv, tha);
    k_attn<<<dim3(8, 64), 512, ATTN_SMEM>>>();
    k_tail<<<NROWS/32, 64>>>(x, bo, g1, be1, thf, b1, b2, g2, be2, out);
}